// round 12
// baseline (speedup 1.0000x reference)
#include <cuda_runtime.h>
#include <cuda_fp16.h>
#include <math.h>
#include <stdint.h>

#define B_  4
#define H_  16
#define LQ_ 512
#define LK_ 2048
#define DM_ 1024

#define XQ_ROW 0
#define XK_ROW 2048
#define XV_ROW (2048 + 8192)

// ---------------------------------------------------------------------------
// Scratch (device globals; no runtime allocation allowed)
// ---------------------------------------------------------------------------
__device__ __align__(16) __half    g_wt [(size_t)4 * DM_ * DM_];     // W^T [mat][n][k] fp16
__device__ __align__(16) __half    g_x  [(size_t)18432 * DM_];       // X fp16 [row][k]
__device__ __align__(16) uint32_t  g_q  [(size_t)B_*H_*LQ_*32];      // q [b,h,l,dpair] half2
__device__ __align__(16) uint32_t  g_k  [(size_t)B_*H_*LK_*32];      // k [b,h,l,dpair] half2
__device__ __align__(16) __half    g_vt [(size_t)B_*H_*64*LK_];      // V^T [b,h,d,key] fp16
__device__ __align__(16) uint32_t  g_ao [(size_t)B_*LQ_*512];        // attn out [row][dpair] half2
__device__ __align__(16) float     g_y  [(size_t)B_*LQ_*DM_];        // pre-LN

// ---------------------------------------------------------------------------
// helpers
// ---------------------------------------------------------------------------
__device__ __forceinline__ uint32_t packh(float e, float o) {
    uint32_t r;
    asm("cvt.rn.f16x2.f32 %0, %1, %2;" : "=r"(r) : "f"(o), "f"(e));
    return r;
}

__device__ __forceinline__ void mma_f16(float c[4],
                                        uint32_t a0, uint32_t a1, uint32_t a2, uint32_t a3,
                                        uint32_t b0, uint32_t b1)
{
    asm volatile(
        "mma.sync.aligned.m16n8k16.row.col.f32.f16.f16.f32 "
        "{%0,%1,%2,%3}, {%4,%5,%6,%7}, {%8,%9}, {%0,%1,%2,%3};"
        : "+f"(c[0]), "+f"(c[1]), "+f"(c[2]), "+f"(c[3])
        : "r"(a0), "r"(a1), "r"(a2), "r"(a3), "r"(b0), "r"(b1));
}

__device__ __forceinline__ void ldsm4(uint32_t& r0, uint32_t& r1, uint32_t& r2, uint32_t& r3,
                                      uint32_t addr)
{
    asm volatile("ldmatrix.sync.aligned.m8n8.x4.shared.b16 {%0,%1,%2,%3}, [%4];"
                 : "=r"(r0), "=r"(r1), "=r"(r2), "=r"(r3) : "r"(addr));
}

__device__ __forceinline__ uint32_t smem_u32(const void* p) {
    uint32_t a;
    asm("{ .reg .u64 t; cvta.to.shared.u64 t, %1; cvt.u32.u64 %0, t; }" : "=r"(a) : "l"(p));
    return a;
}

// ---------------------------------------------------------------------------
// Pre-pass: all X fp32 -> fp16, one launch.
// ---------------------------------------------------------------------------
__global__ void convert_x_all(const float* __restrict__ Q, const float* __restrict__ K,
                              const float* __restrict__ V, __half* __restrict__ dst)
{
    const int row = blockIdx.x;
    const float* src;
    int lr;
    if (row < 2048)       { src = Q; lr = row; }
    else if (row < 10240) { src = K; lr = row - 2048; }
    else                  { src = V; lr = row - 10240; }
    float4 v = ((const float4*)(src + (size_t)lr * DM_))[threadIdx.x];
    uint2 p;
    p.x = packh(v.x, v.y);
    p.y = packh(v.z, v.w);
    ((uint2*)(dst + (size_t)row * DM_))[threadIdx.x] = p;
}

// Pre-pass: all W [k][n] fp32 -> W^T [n][k] fp16 (z = matrix)
__global__ void convert_wt_all(const float* __restrict__ W0, const float* __restrict__ W1,
                               const float* __restrict__ W2, const float* __restrict__ W3,
                               __half* __restrict__ T)
{
    __shared__ float tile[64][65];
    const int z = blockIdx.z;
    const float* W = (z == 0) ? W0 : (z == 1) ? W1 : (z == 2) ? W2 : W3;
    __half* Tz = T + (size_t)z * DM_ * DM_;
    const int n0 = blockIdx.x * 64, k0 = blockIdx.y * 64;
    const int tid = threadIdx.x;
    #pragma unroll
    for (int i = 0; i < 16; i++) {
        int idx = tid + i * 256;
        int r = idx >> 6, c = idx & 63;
        tile[r][c] = W[(size_t)(k0 + r) * DM_ + n0 + c];
    }
    __syncthreads();
    #pragma unroll
    for (int i = 0; i < 16; i++) {
        int idx = tid + i * 256;
        int nr = idx >> 6, kc = idx & 63;
        Tz[(size_t)(n0 + nr) * DM_ + k0 + kc] = __float2half(tile[kc][nr]);
    }
}

// ---------------------------------------------------------------------------
// fp16 GEMM: smem double-buffered (1 sync/tile) + reg prefetch + ldmatrix.
// CTA 128x128, BK=32 (16 kpairs), 256 thr (8 warps 2x4), warp tile 64x32.
// blockIdx.z selects operand set {0,1} (merged K/V launch; single otherwise).
// outMode: 0 -> g_q, 1 -> g_k, 2 -> g_vt (V^T), 3 -> g_y (+resid)
// ---------------------------------------------------------------------------
#define G_STG (2 * 128 * 20)            // u32 per stage (A tile + B tile)
#define GEMM_SMEM (2 * G_STG * 4)

__global__ __launch_bounds__(256, 2)
void gemm_h(const __half* __restrict__ A_g0, const __half* __restrict__ A_g1,
            const __half* __restrict__ B_g0, const __half* __restrict__ B_g1,
            const float* __restrict__ bias0, const float* __restrict__ bias1,
            const float* __restrict__ resid,
            int L, int mode0, int mode1)
{
    extern __shared__ uint32_t sm[];

    const int z = blockIdx.z;
    const uint32_t* a32 = (const uint32_t*)(z ? A_g1 : A_g0);
    const uint32_t* b32 = (const uint32_t*)(z ? B_g1 : B_g0);
    const float* bias   = z ? bias1 : bias0;
    const int outMode   = z ? mode1 : mode0;

    const int row0 = blockIdx.y * 128;
    const int col0 = blockIdx.x * 128;
    const int tid  = threadIdx.x;
    const int lane = tid & 31;
    const int w    = tid >> 5;
    const int wm   = (w >> 2) * 64;
    const int wn   = (w & 3) * 32;
    const int grp  = lane >> 2;
    const int tg   = lane & 3;

    // ldmatrix per-lane row-address offsets (u32 units), loop-invariant.
    const int aoff = (((lane >> 3) & 1) * 8 + (lane & 7)) * 20 + (lane >> 4) * 4;
    const int boff = ((lane >> 4) * 8 + (lane & 7)) * 20 + ((lane >> 3) & 1) * 4;

    const uint32_t sbase = smem_u32(sm);
    const uint32_t sA = sbase + 4 * aoff;                  // + stage*G_STG*4 + row offs
    const uint32_t sB = sbase + 4 * (128 * 20 + boff);

    float acc[4][4][4] = {};

    const int fm = tid >> 1;            // 0..127 (row)
    const int fo = (tid & 1) * 8;       // u32 offset {0,8}

    uint4 pA0, pA1, pB0, pB1;
    auto gload = [&](int kp0) {
        const size_t ga = (size_t)(row0 + fm) * 512 + kp0 + fo;
        const size_t gb = (size_t)(col0 + fm) * 512 + kp0 + fo;
        pA0 = *(const uint4*)&a32[ga];
        pA1 = *(const uint4*)&a32[ga + 4];
        pB0 = *(const uint4*)&b32[gb];
        pB1 = *(const uint4*)&b32[gb + 4];
    };
    auto sts = [&](int s) {
        uint32_t* As = sm + s * G_STG;
        uint32_t* Bs = As + 128 * 20;
        *(uint4*)&As[fm * 20 + fo]     = pA0;
        *(uint4*)&As[fm * 20 + fo + 4] = pA1;
        *(uint4*)&Bs[fm * 20 + fo]     = pB0;
        *(uint4*)&Bs[fm * 20 + fo + 4] = pB1;
    };

    gload(0);
    sts(0);
    __syncthreads();

    for (int t = 0; t < 32; t++) {
        if (t < 31) gload((t + 1) * 16);

        const uint32_t stg = (uint32_t)(t & 1) * (G_STG * 4);
        #pragma unroll
        for (int kt = 0; kt < 2; kt++) {
            const int kb = kt * 8;
            uint32_t bf[4][2];
            #pragma unroll
            for (int np = 0; np < 2; np++) {
                uint32_t addrB = sB + stg + 4 * ((wn + np * 16) * 20 + kb);
                ldsm4(bf[2*np][0], bf[2*np][1], bf[2*np+1][0], bf[2*np+1][1], addrB);
            }
            #pragma unroll
            for (int m = 0; m < 4; m++) {
                uint32_t addrA = sA + stg + 4 * ((wm + m * 16) * 20 + kb);
                uint32_t a0, a1, a2, a3;
                ldsm4(a0, a1, a2, a3, addrA);
                #pragma unroll
                for (int nt = 0; nt < 4; nt++)
                    mma_f16(acc[m][nt], a0, a1, a2, a3, bf[nt][0], bf[nt][1]);
            }
        }

        if (t < 31) {
            sts((t + 1) & 1);
            __syncthreads();
        }
    }

    // ---- epilogue ----
    #pragma unroll
    for (int nt = 0; nt < 4; nt++) {
        const int gc = col0 + wn + nt * 8 + tg * 2;
        const float b0 = bias[gc], b1 = bias[gc + 1];
        #pragma unroll
        for (int m = 0; m < 4; m++) {
            int r0 = row0 + wm + m * 16 + grp;
            int r1 = r0 + 8;
            float v00 = acc[m][nt][0] + b0, v01 = acc[m][nt][1] + b1;
            float v10 = acc[m][nt][2] + b0, v11 = acc[m][nt][3] + b1;
            if (outMode == 3) {
                float2 rr0 = *(const float2*)&resid[(size_t)r0 * DM_ + gc];
                float2 rr1 = *(const float2*)&resid[(size_t)r1 * DM_ + gc];
                float2 o0 = {v00 + rr0.x, v01 + rr0.y};
                float2 o1 = {v10 + rr1.x, v11 + rr1.y};
                *(float2*)&g_y[(size_t)r0 * DM_ + gc] = o0;
                *(float2*)&g_y[(size_t)r1 * DM_ + gc] = o1;
            } else if (outMode == 2) {
                const int hh = gc >> 6, d = gc & 63;
                const int b0i = r0 / L, k0i = r0 % L;
                const int b1i = r1 / L, k1i = r1 % L;
                size_t base0 = (size_t)(b0i * H_ + hh) * 64;
                size_t base1 = (size_t)(b1i * H_ + hh) * 64;
                g_vt[(base0 + d)     * LK_ + k0i] = __float2half(v00);
                g_vt[(base0 + d + 1) * LK_ + k0i] = __float2half(v01);
                g_vt[(base1 + d)     * LK_ + k1i] = __float2half(v10);
                g_vt[(base1 + d + 1) * LK_ + k1i] = __float2half(v11);
            } else {
                const int hh = gc >> 6, dp = (gc & 63) >> 1;
                const int b0i = r0 / L, ll0 = r0 % L;
                const int b1i = r1 / L, ll1 = r1 % L;
                uint32_t* oq = (outMode == 0) ? g_q : g_k;
                oq[((size_t)(b0i * H_ + hh) * L + ll0) * 32 + dp] = packh(v00, v01);
                oq[((size_t)(b1i * H_ + hh) * L + ll1) * 32 + dp] = packh(v10, v11);
            }
        }
    }
}

// ---------------------------------------------------------------------------
// fp16 flash attention: smem double-buffered K/V (1 sync/tile) + reg prefetch
// + ldmatrix. Block (64q, h, b), 128 thr (4 warps, warp = 16 q rows).
// ---------------------------------------------------------------------------
#define FS_Q 0
#define F_STG (2 * 64 * 36 + 64)        // u32 per stage: K tile, V tile, mask
#define FA_SMEM ((64 * 36 + 2 * F_STG) * 4)

__global__ __launch_bounds__(128)
void flash_attn(const int* __restrict__ mask)
{
    extern __shared__ uint32_t sm[];
    uint32_t* Qs = sm + FS_Q;

    const int q0 = blockIdx.x * 64, h = blockIdx.y, b = blockIdx.z;
    const int tid  = threadIdx.x;
    const int lane = tid & 31;
    const int w    = tid >> 5;
    const int grp  = lane >> 2;
    const int tg   = lane & 3;

    const size_t bh_off = (size_t)(b * H_ + h);
    const uint32_t* kq_g = g_k + bh_off * LK_ * 32;
    const uint32_t* vt32 = (const uint32_t*)(g_vt + bh_off * 64 * LK_);
    const int* mk_g = mask + b * LK_;

    const int fr = tid >> 1, fh = (tid & 1) * 16;

    // ldmatrix B-type per-lane offsets (stride 36 layout)
    const int koff = ((lane >> 4) * 8 + (lane & 7)) * 36 + ((lane >> 3) & 1) * 4;
    const uint32_t sbase = smem_u32(sm);
    const uint32_t sK = sbase + 4 * (64 * 36 + koff);          // + stage*F_STG*4
    const uint32_t sV = sK + 4 * (64 * 36);

    uint4 pk[4], pv[4];
    int pm;
    auto gload = [&](int k0) {
        #pragma unroll
        for (int i = 0; i < 4; i++) {
            pk[i] = *(const uint4*)&kq_g[(size_t)(k0 + fr) * 32 + fh + i * 4];
            pv[i] = *(const uint4*)&vt32[(size_t)fr * (LK_ / 2) + (k0 >> 1) + fh + i * 4];
        }
        pm = (tid < 64) ? mk_g[k0 + tid] : 0;
    };
    auto sts = [&](int s) {
        uint32_t* Ks = sm + 64 * 36 + s * F_STG;
        uint32_t* Vs = Ks + 64 * 36;
        float*   mk = (float*)(Vs + 64 * 36);
        #pragma unroll
        for (int i = 0; i < 4; i++) {
            *(uint4*)&Ks[fr * 36 + fh + i * 4] = pk[i];
            *(uint4*)&Vs[fr * 36 + fh + i * 4] = pv[i];
        }
        if (tid < 64) mk[tid] = (pm == 0) ? -1e30f : 0.0f;
    };

    // ---- load Q tile + stage 0 ----
    {
        const uint32_t* qg = g_q + (bh_off * LQ_ + q0) * 32;
        #pragma unroll
        for (int i = 0; i < 4; i++)
            *(uint4*)&Qs[fr * 36 + fh + i * 4] = *(const uint4*)&qg[(size_t)fr * 32 + fh + i * 4];
    }
    gload(0);
    sts(0);
    __syncthreads();

    // ---- Q fragments (registers for whole mainloop) ----
    uint32_t qf[4][4];
    {
        const int r = w * 16 + grp;
        #pragma unroll
        for (int kt = 0; kt < 4; kt++) {
            const int kb = kt * 8;
            qf[kt][0] = Qs[r * 36 + kb + tg];
            qf[kt][1] = Qs[(r + 8) * 36 + kb + tg];
            qf[kt][2] = Qs[r * 36 + kb + tg + 4];
            qf[kt][3] = Qs[(r + 8) * 36 + kb + tg + 4];
        }
    }

    float oacc[8][4];
    #pragma unroll
    for (int nt = 0; nt < 8; nt++)
        #pragma unroll
        for (int j = 0; j < 4; j++) oacc[nt][j] = 0.f;
    float m0 = -1e30f, m1 = -1e30f, lsum0 = 0.f, lsum1 = 0.f;

    const int NT = LK_ / 64;
    for (int t = 0; t < NT; t++) {
        if (t + 1 < NT) gload((t + 1) * 64);

        const uint32_t stg = (uint32_t)(t & 1) * (F_STG * 4);
        const float* msk = (const float*)(sm + 64 * 36 + (t & 1) * F_STG + 2 * 64 * 36);

        // ---- S = Q K^T ----
        float s[8][4];
        #pragma unroll
        for (int nt = 0; nt < 8; nt++)
            #pragma unroll
            for (int j = 0; j < 4; j++) s[nt][j] = 0.f;

        #pragma unroll
        for (int kt = 0; kt < 4; kt++) {
            const int kb = kt * 8;
            #pragma unroll
            for (int np = 0; np < 4; np++) {
                uint32_t b0, b1, b2, b3;
                ldsm4(b0, b1, b2, b3, sK + stg + 4 * (np * 16 * 36 + kb));
                mma_f16(s[2*np],   qf[kt][0], qf[kt][1], qf[kt][2], qf[kt][3], b0, b1);
                mma_f16(s[2*np+1], qf[kt][0], qf[kt][1], qf[kt][2], qf[kt][3], b2, b3);
            }
        }

        // ---- online softmax ----
        const float scl = 0.125f;
        float rmax0 = -1e30f, rmax1 = -1e30f;
        #pragma unroll
        for (int nt = 0; nt < 8; nt++) {
            float mk0 = msk[nt * 8 + 2 * tg];
            float mk1 = msk[nt * 8 + 2 * tg + 1];
            s[nt][0] = s[nt][0] * scl + mk0;
            s[nt][1] = s[nt][1] * scl + mk1;
            s[nt][2] = s[nt][2] * scl + mk0;
            s[nt][3] = s[nt][3] * scl + mk1;
            rmax0 = fmaxf(rmax0, fmaxf(s[nt][0], s[nt][1]));
            rmax1 = fmaxf(rmax1, fmaxf(s[nt][2], s[nt][3]));
        }
        rmax0 = fmaxf(rmax0, __shfl_xor_sync(0xffffffffu, rmax0, 1));
        rmax0 = fmaxf(rmax0, __shfl_xor_sync(0xffffffffu, rmax0, 2));
        rmax1 = fmaxf(rmax1, __shfl_xor_sync(0xffffffffu, rmax1, 1));
        rmax1 = fmaxf(rmax1, __shfl_xor_sync(0xffffffffu, rmax1, 2));

        float mn0 = fmaxf(m0, rmax0), mn1 = fmaxf(m1, rmax1);
        float c0 = __expf(m0 - mn0),  c1 = __expf(m1 - mn1);
        m0 = mn0; m1 = mn1;

        float sum0 = 0.f, sum1 = 0.f;
        #pragma unroll
        for (int nt = 0; nt < 8; nt++) {
            s[nt][0] = __expf(s[nt][0] - mn0);
            s[nt][1] = __expf(s[nt][1] - mn0);
            s[nt][2] = __expf(s[nt][2] - mn1);
            s[nt][3] = __expf(s[nt][3] - mn1);
            sum0 += s[nt][0] + s[nt][1];
            sum1 += s[nt][2] + s[nt][3];
        }
        sum0 += __shfl_xor_sync(0xffffffffu, sum0, 1);
        sum0 += __shfl_xor_sync(0xffffffffu, sum0, 2);
        sum1 += __shfl_xor_sync(0xffffffffu, sum1, 1);
        sum1 += __shfl_xor_sync(0xffffffffu, sum1, 2);
        lsum0 = lsum0 * c0 + sum0;
        lsum1 = lsum1 * c1 + sum1;

        #pragma unroll
        for (int nt = 0; nt < 8; nt++) {
            oacc[nt][0] *= c0; oacc[nt][1] *= c0;
            oacc[nt][2] *= c1; oacc[nt][3] *= c1;
        }

        // ---- O += P V ----
        #pragma unroll
        for (int kg = 0; kg < 4; kg++) {
            uint32_t pa0 = packh(s[2*kg][0],   s[2*kg][1]);
            uint32_t pa1 = packh(s[2*kg][2],   s[2*kg][3]);
            uint32_t pa2 = packh(s[2*kg+1][0], s[2*kg+1][1]);
            uint32_t pa3 = packh(s[2*kg+1][2], s[2*kg+1][3]);
            const int kb = kg * 8;
            #pragma unroll
            for (int np = 0; np < 4; np++) {
                uint32_t b0, b1, b2, b3;
                ldsm4(b0, b1, b2, b3, sV + stg + 4 * (np * 16 * 36 + kb));
                mma_f16(oacc[2*np],   pa0, pa1, pa2, pa3, b0, b1);
                mma_f16(oacc[2*np+1], pa0, pa1, pa2, pa3, b2, b3);
            }
        }

        if (t + 1 < NT) {
            sts((t + 1) & 1);
            __syncthreads();
        }
    }

    // ---- epilogue: packed fp16 attention output ----
    float inv0 = 1.0f / lsum0, inv1 = 1.0f / lsum1;
    int qr0 = q0 + w * 16 + grp;
    int qr1 = qr0 + 8;
    size_t r0base = ((size_t)b * LQ_ + qr0) * 512 + h * 32;
    size_t r1base = ((size_t)b * LQ_ + qr1) * 512 + h * 32;
    #pragma unroll
    for (int nt = 0; nt < 8; nt++) {
        int dp = nt * 4 + tg;
        g_ao[r0base + dp] = packh(oacc[nt][0] * inv0, oacc[nt][1] * inv0);
        g_ao[r1base + dp] = packh(oacc[nt][2] * inv1, oacc[nt][3] * inv1);
    }
}

// ---------------------------------------------------------------------------
// LayerNorm per row of g_y
// ---------------------------------------------------------------------------
__global__ void layernorm_kernel(const float* __restrict__ gamma,
                                 const float* __restrict__ beta,
                                 float* __restrict__ out)
{
    const int row = blockIdx.x;
    const int tid = threadIdx.x;
    __shared__ float red[256];

    const float* yr = g_y + (size_t)row * DM_;
    float4 xv = *(const float4*)(yr + tid * 4);

    float s = xv.x + xv.y + xv.z + xv.w;
    red[tid] = s; __syncthreads();
    #pragma unroll
    for (int st = 128; st > 0; st >>= 1) {
        if (tid < st) red[tid] += red[tid + st];
        __syncthreads();
    }
    float mean = red[0] * (1.0f / DM_);
    __syncthreads();

    float dx = xv.x - mean, dy = xv.y - mean, dz = xv.z - mean, dw = xv.w - mean;
    float sq = dx * dx + dy * dy + dz * dz + dw * dw;
    red[tid] = sq; __syncthreads();
    #pragma unroll
    for (int st = 128; st > 0; st >>= 1) {
        if (tid < st) red[tid] += red[tid + st];
        __syncthreads();
    }
    float rstd = rsqrtf(red[0] * (1.0f / DM_) + 1e-5f);

    int n = tid * 4;
    float4 ov;
    ov.x = dx * rstd * gamma[n]     + beta[n];
    ov.y = dy * rstd * gamma[n + 1] + beta[n + 1];
    ov.z = dz * rstd * gamma[n + 2] + beta[n + 2];
    ov.w = dw * rstd * gamma[n + 3] + beta[n + 3];
    *(float4*)(out + (size_t)row * DM_ + n) = ov;
}

// ---------------------------------------------------------------------------
extern "C" void kernel_launch(void* const* d_in, const int* in_sizes, int n_in,
                              void* d_out, int out_size)
{
    const float* Q    = (const float*)d_in[0];
    const float* K    = (const float*)d_in[1];
    const float* V    = (const float*)d_in[2];
    /* d_in[3] = node_num (unused) */
    const int*   mask = (const int*)  d_in[4];
    const float* Wq   = (const float*)d_in[5];
    const float* bq   = (const float*)d_in[6];
    const float* Wk   = (const float*)d_in[7];
    const float* bk   = (const float*)d_in[8];
    const float* Wv   = (const float*)d_in[9];
    const float* bv   = (const float*)d_in[10];
    const float* Wo   = (const float*)d_in[11];
    const float* bo   = (const float*)d_in[12];
    const float* gamma= (const float*)d_in[13];
    const float* beta = (const float*)d_in[14];
    float* out = (float*)d_out;

    cudaFuncSetAttribute(gemm_h,     cudaFuncAttributeMaxDynamicSharedMemorySize, GEMM_SMEM);
    cudaFuncSetAttribute(flash_attn, cudaFuncAttributeMaxDynamicSharedMemorySize, FA_SMEM);

    __half *wt, *x;
    uint32_t *ao;
    cudaGetSymbolAddress((void**)&wt, g_wt);
    cudaGetSymbolAddress((void**)&x,  g_x);
    cudaGetSymbolAddress((void**)&ao, g_ao);

    const size_t WS = (size_t)DM_ * DM_;

    // ---- pre-pass conversions (2 launches) ----
    convert_wt_all<<<dim3(16, 16, 4), 256>>>(Wq, Wk, Wv, Wo, wt);
    convert_x_all<<<18432, 256>>>(Q, K, V, x);

    // ---- Q projection ----
    gemm_h<<<dim3(8, 16, 1), 256, GEMM_SMEM>>>(
        x + (size_t)XQ_ROW * DM_, x + (size_t)XQ_ROW * DM_,
        wt + 0 * WS, wt + 0 * WS, bq, bq, nullptr, LQ_, 0, 0);

    // ---- K + V projections (merged launch, z selects) ----
    gemm_h<<<dim3(8, 64, 2), 256, GEMM_SMEM>>>(
        x + (size_t)XK_ROW * DM_, x + (size_t)XV_ROW * DM_,
        wt + 1 * WS, wt + 2 * WS, bk, bv, nullptr, LK_, 1, 2);

    // ---- attention ----
    flash_attn<<<dim3(LQ_ / 64, H_, B_), 128, FA_SMEM>>>(mask);

    // ---- output projection + residual ----
    gemm_h<<<dim3(8, 16, 1), 256, GEMM_SMEM>>>(
        (const __half*)ao, (const __half*)ao,
        wt + 3 * WS, wt + 3 * WS, bo, bo, Q, LQ_, 3, 3);

    // ---- layernorm ----
    layernorm_kernel<<<B_ * LQ_, 256>>>(gamma, beta, out);
}

// round 13
// speedup vs baseline: 1.1576x; 1.1576x over previous
#include <cuda_runtime.h>
#include <cuda_fp16.h>
#include <math.h>
#include <stdint.h>

#define B_  4
#define H_  16
#define LQ_ 512
#define LK_ 2048
#define DM_ 1024

#define XQ_ROW 0
#define XK_ROW 2048
#define XV_ROW (2048 + 8192)

// ---------------------------------------------------------------------------
// Scratch (device globals; no runtime allocation allowed)
// ---------------------------------------------------------------------------
__device__ __align__(16) __half    g_wt [(size_t)4 * DM_ * DM_];     // W^T [mat][n][k] fp16
__device__ __align__(16) __half    g_x  [(size_t)18432 * DM_];       // X fp16 [row][k]
__device__ __align__(16) uint32_t  g_q  [(size_t)B_*H_*LQ_*32];      // q [b,h,l,dpair] half2
__device__ __align__(16) uint32_t  g_k  [(size_t)B_*H_*LK_*32];      // k [b,h,l,dpair] half2
__device__ __align__(16) __half    g_vt [(size_t)B_*H_*64*LK_];      // V^T [b,h,d,key] fp16
__device__ __align__(16) uint32_t  g_ao [(size_t)B_*LQ_*512];        // attn out [row][dpair] half2
__device__ __align__(16) float     g_y  [(size_t)B_*LQ_*DM_];        // pre-LN

// ---------------------------------------------------------------------------
// helpers
// ---------------------------------------------------------------------------
__device__ __forceinline__ uint32_t packh(float e, float o) {
    uint32_t r;
    asm("cvt.rn.f16x2.f32 %0, %1, %2;" : "=r"(r) : "f"(o), "f"(e));
    return r;
}

__device__ __forceinline__ void mma_f16(float c[4],
                                        uint32_t a0, uint32_t a1, uint32_t a2, uint32_t a3,
                                        uint32_t b0, uint32_t b1)
{
    asm volatile(
        "mma.sync.aligned.m16n8k16.row.col.f32.f16.f16.f32 "
        "{%0,%1,%2,%3}, {%4,%5,%6,%7}, {%8,%9}, {%0,%1,%2,%3};"
        : "+f"(c[0]), "+f"(c[1]), "+f"(c[2]), "+f"(c[3])
        : "r"(a0), "r"(a1), "r"(a2), "r"(a3), "r"(b0), "r"(b1));
}

__device__ __forceinline__ void ldsm4(uint32_t& r0, uint32_t& r1, uint32_t& r2, uint32_t& r3,
                                      uint32_t addr)
{
    asm volatile("ldmatrix.sync.aligned.m8n8.x4.shared.b16 {%0,%1,%2,%3}, [%4];"
                 : "=r"(r0), "=r"(r1), "=r"(r2), "=r"(r3) : "r"(addr));
}

__device__ __forceinline__ uint32_t smem_u32(const void* p) {
    uint32_t a;
    asm("{ .reg .u64 t; cvta.to.shared.u64 t, %1; cvt.u32.u64 %0, t; }" : "=r"(a) : "l"(p));
    return a;
}

#define CP16(dst, src) \
    asm volatile("cp.async.cg.shared.global [%0], [%1], 16;" :: "r"(dst), "l"(src) : "memory")
#define CPCOMMIT() asm volatile("cp.async.commit_group;" ::: "memory")
#define CPWAIT1()  asm volatile("cp.async.wait_group 1;" ::: "memory")
#define CPWAIT0()  asm volatile("cp.async.wait_group 0;" ::: "memory")

// ---------------------------------------------------------------------------
// Pre-pass: all X fp32 -> fp16, one launch.
// ---------------------------------------------------------------------------
__global__ void convert_x_all(const float* __restrict__ Q, const float* __restrict__ K,
                              const float* __restrict__ V, __half* __restrict__ dst)
{
    const int row = blockIdx.x;
    const float* src;
    int lr;
    if (row < 2048)       { src = Q; lr = row; }
    else if (row < 10240) { src = K; lr = row - 2048; }
    else                  { src = V; lr = row - 10240; }
    float4 v = ((const float4*)(src + (size_t)lr * DM_))[threadIdx.x];
    uint2 p;
    p.x = packh(v.x, v.y);
    p.y = packh(v.z, v.w);
    ((uint2*)(dst + (size_t)row * DM_))[threadIdx.x] = p;
}

// Pre-pass: all W [k][n] fp32 -> W^T [n][k] fp16 (z = matrix)
__global__ void convert_wt_all(const float* __restrict__ W0, const float* __restrict__ W1,
                               const float* __restrict__ W2, const float* __restrict__ W3,
                               __half* __restrict__ T)
{
    __shared__ float tile[64][65];
    const int z = blockIdx.z;
    const float* W = (z == 0) ? W0 : (z == 1) ? W1 : (z == 2) ? W2 : W3;
    __half* Tz = T + (size_t)z * DM_ * DM_;
    const int n0 = blockIdx.x * 64, k0 = blockIdx.y * 64;
    const int tid = threadIdx.x;
    #pragma unroll
    for (int i = 0; i < 16; i++) {
        int idx = tid + i * 256;
        int r = idx >> 6, c = idx & 63;
        tile[r][c] = W[(size_t)(k0 + r) * DM_ + n0 + c];
    }
    __syncthreads();
    #pragma unroll
    for (int i = 0; i < 16; i++) {
        int idx = tid + i * 256;
        int nr = idx >> 6, kc = idx & 63;
        Tz[(size_t)(n0 + nr) * DM_ + k0 + kc] = __float2half(tile[kc][nr]);
    }
}

// ---------------------------------------------------------------------------
// fp16 GEMM: CTA 128x128, 128 thr (4 warps 2x2), warp tile 64x64.
// 3-stage cp.async pipeline, 1 syncthreads per k-tile, ldmatrix fragments.
// blockIdx.z selects operand set {0,1}.
// outMode: 0 -> g_q, 1 -> g_k, 2 -> g_vt (V^T), 3 -> g_y (+resid)
// ---------------------------------------------------------------------------
#define G_STG (2 * 128 * 20)            // u32 per stage (A tile + B tile)
#define GEMM_SMEM (3 * G_STG * 4)

__global__ __launch_bounds__(128)
void gemm_h(const __half* __restrict__ A_g0, const __half* __restrict__ A_g1,
            const __half* __restrict__ B_g0, const __half* __restrict__ B_g1,
            const float* __restrict__ bias0, const float* __restrict__ bias1,
            const float* __restrict__ resid,
            int L, int mode0, int mode1)
{
    extern __shared__ uint32_t sm[];

    const int z = blockIdx.z;
    const uint32_t* a32 = (const uint32_t*)(z ? A_g1 : A_g0);
    const uint32_t* b32 = (const uint32_t*)(z ? B_g1 : B_g0);
    const float* bias   = z ? bias1 : bias0;
    const int outMode   = z ? mode1 : mode0;

    const int row0 = blockIdx.y * 128;
    const int col0 = blockIdx.x * 128;
    const int tid  = threadIdx.x;
    const int lane = tid & 31;
    const int w    = tid >> 5;
    const int wm   = (w >> 1) * 64;     // 0,64
    const int wn   = (w & 1) * 64;      // 0,64
    const int grp  = lane >> 2;
    const int tg   = lane & 3;

    // ldmatrix per-lane row-address offsets (u32 units), loop-invariant.
    const int aoff = (((lane >> 3) & 1) * 8 + (lane & 7)) * 20 + (lane >> 4) * 4;
    const int boff = ((lane >> 4) * 8 + (lane & 7)) * 20 + ((lane >> 3) & 1) * 4;

    const uint32_t sbase = smem_u32(sm);
    const uint32_t sA = sbase + 4 * aoff;
    const uint32_t sB = sbase + 4 * (128 * 20 + boff);

    float acc[4][8][4] = {};

    // cp.async fill: 512 A chunks + 512 B chunks of 16B; 128 thr x 4 each
    const int fr = tid >> 2;            // 0..31 base row
    const int fc = tid & 3;             // chunk 0..3
    auto fill = [&](int s, int kp0) {
        uint32_t* As = sm + s * G_STG;
        uint32_t* Bs = As + 128 * 20;
        #pragma unroll
        for (int i = 0; i < 4; i++) {
            int r = fr + i * 32;
            uint32_t dA = smem_u32(&As[r * 20 + fc * 4]);
            uint32_t dB = smem_u32(&Bs[r * 20 + fc * 4]);
            CP16(dA, &a32[(size_t)(row0 + r) * 512 + kp0 + fc * 4]);
            CP16(dB, &b32[(size_t)(col0 + r) * 512 + kp0 + fc * 4]);
        }
        CPCOMMIT();
    };

    fill(0, 0);
    fill(1, 16);
    CPWAIT1();
    __syncthreads();    // stage 0 ready

    for (int t = 0; t < 32; t++) {
        if (t + 2 < 32) fill((t + 2) % 3, (t + 2) * 16);

        const uint32_t stg = (uint32_t)((t % 3) * (G_STG * 4));
        #pragma unroll
        for (int kt = 0; kt < 2; kt++) {
            const int kb = kt * 8;
            uint32_t bf[8][2];
            #pragma unroll
            for (int np = 0; np < 4; np++) {
                uint32_t addrB = sB + stg + 4 * ((wn + np * 16) * 20 + kb);
                ldsm4(bf[2*np][0], bf[2*np][1], bf[2*np+1][0], bf[2*np+1][1], addrB);
            }
            #pragma unroll
            for (int m = 0; m < 4; m++) {
                uint32_t addrA = sA + stg + 4 * ((wm + m * 16) * 20 + kb);
                uint32_t a0, a1, a2, a3;
                ldsm4(a0, a1, a2, a3, addrA);
                #pragma unroll
                for (int nt = 0; nt < 8; nt++)
                    mma_f16(acc[m][nt], a0, a1, a2, a3, bf[nt][0], bf[nt][1]);
            }
        }

        if (t + 1 < 32) {
            if (t + 2 < 32) CPWAIT1(); else CPWAIT0();
            __syncthreads();
        }
    }

    // ---- epilogue ----
    #pragma unroll
    for (int nt = 0; nt < 8; nt++) {
        const int gc = col0 + wn + nt * 8 + tg * 2;
        const float b0 = bias[gc], b1 = bias[gc + 1];
        #pragma unroll
        for (int m = 0; m < 4; m++) {
            int r0 = row0 + wm + m * 16 + grp;
            int r1 = r0 + 8;
            float v00 = acc[m][nt][0] + b0, v01 = acc[m][nt][1] + b1;
            float v10 = acc[m][nt][2] + b0, v11 = acc[m][nt][3] + b1;
            if (outMode == 3) {
                float2 rr0 = *(const float2*)&resid[(size_t)r0 * DM_ + gc];
                float2 rr1 = *(const float2*)&resid[(size_t)r1 * DM_ + gc];
                float2 o0 = {v00 + rr0.x, v01 + rr0.y};
                float2 o1 = {v10 + rr1.x, v11 + rr1.y};
                *(float2*)&g_y[(size_t)r0 * DM_ + gc] = o0;
                *(float2*)&g_y[(size_t)r1 * DM_ + gc] = o1;
            } else if (outMode == 2) {
                const int hh = gc >> 6, d = gc & 63;
                const int b0i = r0 / L, k0i = r0 % L;
                const int b1i = r1 / L, k1i = r1 % L;
                size_t base0 = (size_t)(b0i * H_ + hh) * 64;
                size_t base1 = (size_t)(b1i * H_ + hh) * 64;
                g_vt[(base0 + d)     * LK_ + k0i] = __float2half(v00);
                g_vt[(base0 + d + 1) * LK_ + k0i] = __float2half(v01);
                g_vt[(base1 + d)     * LK_ + k1i] = __float2half(v10);
                g_vt[(base1 + d + 1) * LK_ + k1i] = __float2half(v11);
            } else {
                const int hh = gc >> 6, dp = (gc & 63) >> 1;
                const int b0i = r0 / L, ll0 = r0 % L;
                const int b1i = r1 / L, ll1 = r1 % L;
                uint32_t* oq = (outMode == 0) ? g_q : g_k;
                oq[((size_t)(b0i * H_ + hh) * L + ll0) * 32 + dp] = packh(v00, v01);
                oq[((size_t)(b1i * H_ + hh) * L + ll1) * 32 + dp] = packh(v10, v11);
            }
        }
    }
}

// ---------------------------------------------------------------------------
// fp16 flash attention (R11 version): reg-prefetched K/V, single-buffered
// smem (2 syncs/tile), ldmatrix fragments. Block (64q, h, b), 128 thr.
// ---------------------------------------------------------------------------
#define FS_Q 0
#define FS_K (64 * 36)
#define FS_V (2 * 64 * 36)
#define FS_MSK (3 * 64 * 36)
#define FA_SMEM ((FS_MSK + 64) * 4)

__global__ __launch_bounds__(128)
void flash_attn(const int* __restrict__ mask)
{
    extern __shared__ uint32_t sm[];
    uint32_t* Qs = sm + FS_Q;
    uint32_t* Ks = sm + FS_K;
    uint32_t* Vs = sm + FS_V;
    float*   msk = (float*)(sm + FS_MSK);

    const int q0 = blockIdx.x * 64, h = blockIdx.y, b = blockIdx.z;
    const int tid  = threadIdx.x;
    const int lane = tid & 31;
    const int w    = tid >> 5;
    const int grp  = lane >> 2;
    const int tg   = lane & 3;

    const size_t bh_off = (size_t)(b * H_ + h);
    const uint32_t* kq_g = g_k + bh_off * LK_ * 32;
    const uint32_t* vt32 = (const uint32_t*)(g_vt + bh_off * 64 * LK_);
    const int* mk_g = mask + b * LK_;

    const int fr = tid >> 1, fh = (tid & 1) * 16;

    const int koff = ((lane >> 4) * 8 + (lane & 7)) * 36 + ((lane >> 3) & 1) * 4;
    const uint32_t sK = smem_u32(Ks) + 4 * koff;
    const uint32_t sV = smem_u32(Vs) + 4 * koff;

    uint4 pk[4], pv[4];
    int pm;
    auto gload = [&](int k0) {
        #pragma unroll
        for (int i = 0; i < 4; i++) {
            pk[i] = *(const uint4*)&kq_g[(size_t)(k0 + fr) * 32 + fh + i * 4];
            pv[i] = *(const uint4*)&vt32[(size_t)fr * (LK_ / 2) + (k0 >> 1) + fh + i * 4];
        }
        pm = (tid < 64) ? mk_g[k0 + tid] : 0;
    };
    auto sts = [&]() {
        #pragma unroll
        for (int i = 0; i < 4; i++) {
            *(uint4*)&Ks[fr * 36 + fh + i * 4] = pk[i];
            *(uint4*)&Vs[fr * 36 + fh + i * 4] = pv[i];
        }
        if (tid < 64) msk[tid] = (pm == 0) ? -1e30f : 0.0f;
    };

    {
        const uint32_t* qg = g_q + (bh_off * LQ_ + q0) * 32;
        #pragma unroll
        for (int i = 0; i < 4; i++)
            *(uint4*)&Qs[fr * 36 + fh + i * 4] = *(const uint4*)&qg[(size_t)fr * 32 + fh + i * 4];
    }
    gload(0);
    sts();
    __syncthreads();

    uint32_t qf[4][4];
    {
        const int r = w * 16 + grp;
        #pragma unroll
        for (int kt = 0; kt < 4; kt++) {
            const int kb = kt * 8;
            qf[kt][0] = Qs[r * 36 + kb + tg];
            qf[kt][1] = Qs[(r + 8) * 36 + kb + tg];
            qf[kt][2] = Qs[r * 36 + kb + tg + 4];
            qf[kt][3] = Qs[(r + 8) * 36 + kb + tg + 4];
        }
    }

    float oacc[8][4];
    #pragma unroll
    for (int nt = 0; nt < 8; nt++)
        #pragma unroll
        for (int j = 0; j < 4; j++) oacc[nt][j] = 0.f;
    float m0 = -1e30f, m1 = -1e30f, lsum0 = 0.f, lsum1 = 0.f;

    const int NT = LK_ / 64;
    for (int t = 0; t < NT; t++) {
        if (t + 1 < NT) gload((t + 1) * 64);

        float s[8][4];
        #pragma unroll
        for (int nt = 0; nt < 8; nt++)
            #pragma unroll
            for (int j = 0; j < 4; j++) s[nt][j] = 0.f;

        #pragma unroll
        for (int kt = 0; kt < 4; kt++) {
            const int kb = kt * 8;
            #pragma unroll
            for (int np = 0; np < 4; np++) {
                uint32_t b0, b1, b2, b3;
                ldsm4(b0, b1, b2, b3, sK + 4 * (np * 16 * 36 + kb));
                mma_f16(s[2*np],   qf[kt][0], qf[kt][1], qf[kt][2], qf[kt][3], b0, b1);
                mma_f16(s[2*np+1], qf[kt][0], qf[kt][1], qf[kt][2], qf[kt][3], b2, b3);
            }
        }

        const float scl = 0.125f;
        float rmax0 = -1e30f, rmax1 = -1e30f;
        #pragma unroll
        for (int nt = 0; nt < 8; nt++) {
            float mk0 = msk[nt * 8 + 2 * tg];
            float mk1 = msk[nt * 8 + 2 * tg + 1];
            s[nt][0] = s[nt][0] * scl + mk0;
            s[nt][1] = s[nt][1] * scl + mk1;
            s[nt][2] = s[nt][2] * scl + mk0;
            s[nt][3] = s[nt][3] * scl + mk1;
            rmax0 = fmaxf(rmax0, fmaxf(s[nt][0], s[nt][1]));
            rmax1 = fmaxf(rmax1, fmaxf(s[nt][2], s[nt][3]));
        }
        rmax0 = fmaxf(rmax0, __shfl_xor_sync(0xffffffffu, rmax0, 1));
        rmax0 = fmaxf(rmax0, __shfl_xor_sync(0xffffffffu, rmax0, 2));
        rmax1 = fmaxf(rmax1, __shfl_xor_sync(0xffffffffu, rmax1, 1));
        rmax1 = fmaxf(rmax1, __shfl_xor_sync(0xffffffffu, rmax1, 2));

        float mn0 = fmaxf(m0, rmax0), mn1 = fmaxf(m1, rmax1);
        float c0 = __expf(m0 - mn0),  c1 = __expf(m1 - mn1);
        m0 = mn0; m1 = mn1;

        float sum0 = 0.f, sum1 = 0.f;
        #pragma unroll
        for (int nt = 0; nt < 8; nt++) {
            s[nt][0] = __expf(s[nt][0] - mn0);
            s[nt][1] = __expf(s[nt][1] - mn0);
            s[nt][2] = __expf(s[nt][2] - mn1);
            s[nt][3] = __expf(s[nt][3] - mn1);
            sum0 += s[nt][0] + s[nt][1];
            sum1 += s[nt][2] + s[nt][3];
        }
        sum0 += __shfl_xor_sync(0xffffffffu, sum0, 1);
        sum0 += __shfl_xor_sync(0xffffffffu, sum0, 2);
        sum1 += __shfl_xor_sync(0xffffffffu, sum1, 1);
        sum1 += __shfl_xor_sync(0xffffffffu, sum1, 2);
        lsum0 = lsum0 * c0 + sum0;
        lsum1 = lsum1 * c1 + sum1;

        #pragma unroll
        for (int nt = 0; nt < 8; nt++) {
            oacc[nt][0] *= c0; oacc[nt][1] *= c0;
            oacc[nt][2] *= c1; oacc[nt][3] *= c1;
        }

        #pragma unroll
        for (int kg = 0; kg < 4; kg++) {
            uint32_t pa0 = packh(s[2*kg][0],   s[2*kg][1]);
            uint32_t pa1 = packh(s[2*kg][2],   s[2*kg][3]);
            uint32_t pa2 = packh(s[2*kg+1][0], s[2*kg+1][1]);
            uint32_t pa3 = packh(s[2*kg+1][2], s[2*kg+1][3]);
            const int kb = kg * 8;
            #pragma unroll
            for (int np = 0; np < 4; np++) {
                uint32_t b0, b1, b2, b3;
                ldsm4(b0, b1, b2, b3, sV + 4 * (np * 16 * 36 + kb));
                mma_f16(oacc[2*np],   pa0, pa1, pa2, pa3, b0, b1);
                mma_f16(oacc[2*np+1], pa0, pa1, pa2, pa3, b2, b3);
            }
        }

        if (t + 1 < NT) {
            __syncthreads();
            sts();
            __syncthreads();
        }
    }

    float inv0 = 1.0f / lsum0, inv1 = 1.0f / lsum1;
    int qr0 = q0 + w * 16 + grp;
    int qr1 = qr0 + 8;
    size_t r0base = ((size_t)b * LQ_ + qr0) * 512 + h * 32;
    size_t r1base = ((size_t)b * LQ_ + qr1) * 512 + h * 32;
    #pragma unroll
    for (int nt = 0; nt < 8; nt++) {
        int dp = nt * 4 + tg;
        g_ao[r0base + dp] = packh(oacc[nt][0] * inv0, oacc[nt][1] * inv0);
        g_ao[r1base + dp] = packh(oacc[nt][2] * inv1, oacc[nt][3] * inv1);
    }
}

// ---------------------------------------------------------------------------
// LayerNorm per row of g_y
// ---------------------------------------------------------------------------
__global__ void layernorm_kernel(const float* __restrict__ gamma,
                                 const float* __restrict__ beta,
                                 float* __restrict__ out)
{
    const int row = blockIdx.x;
    const int tid = threadIdx.x;
    __shared__ float red[256];

    const float* yr = g_y + (size_t)row * DM_;
    float4 xv = *(const float4*)(yr + tid * 4);

    float s = xv.x + xv.y + xv.z + xv.w;
    red[tid] = s; __syncthreads();
    #pragma unroll
    for (int st = 128; st > 0; st >>= 1) {
        if (tid < st) red[tid] += red[tid + st];
        __syncthreads();
    }
    float mean = red[0] * (1.0f / DM_);
    __syncthreads();

    float dx = xv.x - mean, dy = xv.y - mean, dz = xv.z - mean, dw = xv.w - mean;
    float sq = dx * dx + dy * dy + dz * dz + dw * dw;
    red[tid] = sq; __syncthreads();
    #pragma unroll
    for (int st = 128; st > 0; st >>= 1) {
        if (tid < st) red[tid] += red[tid + st];
        __syncthreads();
    }
    float rstd = rsqrtf(red[0] * (1.0f / DM_) + 1e-5f);

    int n = tid * 4;
    float4 ov;
    ov.x = dx * rstd * gamma[n]     + beta[n];
    ov.y = dy * rstd * gamma[n + 1] + beta[n + 1];
    ov.z = dz * rstd * gamma[n + 2] + beta[n + 2];
    ov.w = dw * rstd * gamma[n + 3] + beta[n + 3];
    *(float4*)(out + (size_t)row * DM_ + n) = ov;
}

// ---------------------------------------------------------------------------
extern "C" void kernel_launch(void* const* d_in, const int* in_sizes, int n_in,
                              void* d_out, int out_size)
{
    const float* Q    = (const float*)d_in[0];
    const float* K    = (const float*)d_in[1];
    const float* V    = (const float*)d_in[2];
    /* d_in[3] = node_num (unused) */
    const int*   mask = (const int*)  d_in[4];
    const float* Wq   = (const float*)d_in[5];
    const float* bq   = (const float*)d_in[6];
    const float* Wk   = (const float*)d_in[7];
    const float* bk   = (const float*)d_in[8];
    const float* Wv   = (const float*)d_in[9];
    const float* bv   = (const float*)d_in[10];
    const float* Wo   = (const float*)d_in[11];
    const float* bo   = (const float*)d_in[12];
    const float* gamma= (const float*)d_in[13];
    const float* beta = (const float*)d_in[14];
    float* out = (float*)d_out;

    cudaFuncSetAttribute(gemm_h,     cudaFuncAttributeMaxDynamicSharedMemorySize, GEMM_SMEM);
    cudaFuncSetAttribute(flash_attn, cudaFuncAttributeMaxDynamicSharedMemorySize, FA_SMEM);

    __half *wt, *x;
    uint32_t *ao;
    cudaGetSymbolAddress((void**)&wt, g_wt);
    cudaGetSymbolAddress((void**)&x,  g_x);
    cudaGetSymbolAddress((void**)&ao, g_ao);

    const size_t WS = (size_t)DM_ * DM_;

    // ---- pre-pass conversions (2 launches) ----
    convert_wt_all<<<dim3(16, 16, 4), 256>>>(Wq, Wk, Wv, Wo, wt);
    convert_x_all<<<18432, 256>>>(Q, K, V, x);

    // ---- Q projection ----
    gemm_h<<<dim3(8, 16, 1), 128, GEMM_SMEM>>>(
        x + (size_t)XQ_ROW * DM_, x + (size_t)XQ_ROW * DM_,
        wt + 0 * WS, wt + 0 * WS, bq, bq, nullptr, LQ_, 0, 0);

    // ---- K + V projections (merged launch, z selects) ----
    gemm_h<<<dim3(8, 64, 2), 128, GEMM_SMEM>>>(
        x + (size_t)XK_ROW * DM_, x + (size_t)XV_ROW * DM_,
        wt + 1 * WS, wt + 2 * WS, bk, bv, nullptr, LK_, 1, 2);

    // ---- attention ----
    flash_attn<<<dim3(LQ_ / 64, H_, B_), 128, FA_SMEM>>>(mask);

    // ---- output projection + residual ----
    gemm_h<<<dim3(8, 16, 1), 128, GEMM_SMEM>>>(
        (const __half*)ao, (const __half*)ao,
        wt + 3 * WS, wt + 3 * WS, bo, bo, Q, LQ_, 3, 3);

    // ---- layernorm ----
    layernorm_kernel<<<B_ * LQ_, 256>>>(gamma, beta, out);
}

// round 14
// speedup vs baseline: 1.2865x; 1.1114x over previous
#include <cuda_runtime.h>
#include <cuda_fp16.h>
#include <math.h>
#include <stdint.h>

#define B_  4
#define H_  16
#define LQ_ 512
#define LK_ 2048
#define DM_ 1024

#define XQ_ROW 0
#define XK_ROW 2048
#define XV_ROW (2048 + 8192)

// ---------------------------------------------------------------------------
// Scratch (device globals; no runtime allocation allowed)
// ---------------------------------------------------------------------------
__device__ __align__(16) __half    g_wt [(size_t)4 * DM_ * DM_];     // W^T [mat][n][k] fp16
__device__ __align__(16) __half    g_x  [(size_t)18432 * DM_];       // X fp16 [row][k]
__device__ __align__(16) uint32_t  g_q  [(size_t)B_*H_*LQ_*32];      // q [b,h,l,dpair] half2
__device__ __align__(16) uint32_t  g_k  [(size_t)B_*H_*LK_*32];      // k [b,h,l,dpair] half2
__device__ __align__(16) __half    g_vt [(size_t)B_*H_*64*LK_];      // V^T [b,h,d,key] fp16
__device__ __align__(16) uint32_t  g_ao [(size_t)B_*LQ_*512];        // attn out [row][dpair] half2
__device__ __align__(16) float     g_y  [(size_t)B_*LQ_*DM_];        // pre-LN

// ---------------------------------------------------------------------------
// helpers
// ---------------------------------------------------------------------------
__device__ __forceinline__ uint32_t packh(float e, float o) {
    uint32_t r;
    asm("cvt.rn.f16x2.f32 %0, %1, %2;" : "=r"(r) : "f"(o), "f"(e));
    return r;
}

__device__ __forceinline__ void mma_f16(float c[4],
                                        uint32_t a0, uint32_t a1, uint32_t a2, uint32_t a3,
                                        uint32_t b0, uint32_t b1)
{
    asm volatile(
        "mma.sync.aligned.m16n8k16.row.col.f32.f16.f16.f32 "
        "{%0,%1,%2,%3}, {%4,%5,%6,%7}, {%8,%9}, {%0,%1,%2,%3};"
        : "+f"(c[0]), "+f"(c[1]), "+f"(c[2]), "+f"(c[3])
        : "r"(a0), "r"(a1), "r"(a2), "r"(a3), "r"(b0), "r"(b1));
}

__device__ __forceinline__ void ldsm4(uint32_t& r0, uint32_t& r1, uint32_t& r2, uint32_t& r3,
                                      uint32_t addr)
{
    asm volatile("ldmatrix.sync.aligned.m8n8.x4.shared.b16 {%0,%1,%2,%3}, [%4];"
                 : "=r"(r0), "=r"(r1), "=r"(r2), "=r"(r3) : "r"(addr));
}

__device__ __forceinline__ uint32_t smem_u32(const void* p) {
    uint32_t a;
    asm("{ .reg .u64 t; cvta.to.shared.u64 t, %1; cvt.u32.u64 %0, t; }" : "=r"(a) : "l"(p));
    return a;
}

#define CP16(dst, src) \
    asm volatile("cp.async.cg.shared.global [%0], [%1], 16;" :: "r"(dst), "l"(src) : "memory")
#define CPCOMMIT() asm volatile("cp.async.commit_group;" ::: "memory")
#define CPWAIT1()  asm volatile("cp.async.wait_group 1;" ::: "memory")
#define CPWAIT0()  asm volatile("cp.async.wait_group 0;" ::: "memory")

// ---------------------------------------------------------------------------
// Pre-pass: all X fp32 -> fp16
// ---------------------------------------------------------------------------
__global__ void convert_x_all(const float* __restrict__ Q, const float* __restrict__ K,
                              const float* __restrict__ V, __half* __restrict__ dst)
{
    const int row = blockIdx.x;
    const float* src;
    int lr;
    if (row < 2048)       { src = Q; lr = row; }
    else if (row < 10240) { src = K; lr = row - 2048; }
    else                  { src = V; lr = row - 10240; }
    float4 v = ((const float4*)(src + (size_t)lr * DM_))[threadIdx.x];
    uint2 p;
    p.x = packh(v.x, v.y);
    p.y = packh(v.z, v.w);
    ((uint2*)(dst + (size_t)row * DM_))[threadIdx.x] = p;
}

// Pre-pass: all W [k][n] fp32 -> W^T [n][k] fp16 (z = matrix)
__global__ void convert_wt_all(const float* __restrict__ W0, const float* __restrict__ W1,
                               const float* __restrict__ W2, const float* __restrict__ W3,
                               __half* __restrict__ T)
{
    __shared__ float tile[64][65];
    const int z = blockIdx.z;
    const float* W = (z == 0) ? W0 : (z == 1) ? W1 : (z == 2) ? W2 : W3;
    __half* Tz = T + (size_t)z * DM_ * DM_;
    const int n0 = blockIdx.x * 64, k0 = blockIdx.y * 64;
    const int tid = threadIdx.x;
    #pragma unroll
    for (int i = 0; i < 16; i++) {
        int idx = tid + i * 256;
        int r = idx >> 6, c = idx & 63;
        tile[r][c] = W[(size_t)(k0 + r) * DM_ + n0 + c];
    }
    __syncthreads();
    #pragma unroll
    for (int i = 0; i < 16; i++) {
        int idx = tid + i * 256;
        int nr = idx >> 6, kc = idx & 63;
        Tz[(size_t)(n0 + nr) * DM_ + k0 + kc] = __float2half(tile[kc][nr]);
    }
}

// ---------------------------------------------------------------------------
// fp16 GEMM (R13, unchanged): CTA 128x128, 128 thr, warp tile 64x64.
// 3-stage cp.async, 1 sync/tile, ldmatrix.
// ---------------------------------------------------------------------------
#define G_STG (2 * 128 * 20)
#define GEMM_SMEM (3 * G_STG * 4)

__global__ __launch_bounds__(128)
void gemm_h(const __half* __restrict__ A_g0, const __half* __restrict__ A_g1,
            const __half* __restrict__ B_g0, const __half* __restrict__ B_g1,
            const float* __restrict__ bias0, const float* __restrict__ bias1,
            const float* __restrict__ resid,
            int L, int mode0, int mode1)
{
    extern __shared__ uint32_t sm[];

    const int z = blockIdx.z;
    const uint32_t* a32 = (const uint32_t*)(z ? A_g1 : A_g0);
    const uint32_t* b32 = (const uint32_t*)(z ? B_g1 : B_g0);
    const float* bias   = z ? bias1 : bias0;
    const int outMode   = z ? mode1 : mode0;

    const int row0 = blockIdx.y * 128;
    const int col0 = blockIdx.x * 128;
    const int tid  = threadIdx.x;
    const int lane = tid & 31;
    const int w    = tid >> 5;
    const int wm   = (w >> 1) * 64;
    const int wn   = (w & 1) * 64;
    const int grp  = lane >> 2;
    const int tg   = lane & 3;

    const int aoff = (((lane >> 3) & 1) * 8 + (lane & 7)) * 20 + (lane >> 4) * 4;
    const int boff = ((lane >> 4) * 8 + (lane & 7)) * 20 + ((lane >> 3) & 1) * 4;

    const uint32_t sbase = smem_u32(sm);
    const uint32_t sA = sbase + 4 * aoff;
    const uint32_t sB = sbase + 4 * (128 * 20 + boff);

    float acc[4][8][4] = {};

    const int fr = tid >> 2;
    const int fc = tid & 3;
    auto fill = [&](int s, int kp0) {
        uint32_t* As = sm + s * G_STG;
        uint32_t* Bs = As + 128 * 20;
        #pragma unroll
        for (int i = 0; i < 4; i++) {
            int r = fr + i * 32;
            CP16(smem_u32(&As[r * 20 + fc * 4]), &a32[(size_t)(row0 + r) * 512 + kp0 + fc * 4]);
            CP16(smem_u32(&Bs[r * 20 + fc * 4]), &b32[(size_t)(col0 + r) * 512 + kp0 + fc * 4]);
        }
        CPCOMMIT();
    };

    fill(0, 0);
    fill(1, 16);
    CPWAIT1();
    __syncthreads();

    for (int t = 0; t < 32; t++) {
        if (t + 2 < 32) fill((t + 2) % 3, (t + 2) * 16);

        const uint32_t stg = (uint32_t)((t % 3) * (G_STG * 4));
        #pragma unroll
        for (int kt = 0; kt < 2; kt++) {
            const int kb = kt * 8;
            uint32_t bf[8][2];
            #pragma unroll
            for (int np = 0; np < 4; np++) {
                uint32_t addrB = sB + stg + 4 * ((wn + np * 16) * 20 + kb);
                ldsm4(bf[2*np][0], bf[2*np][1], bf[2*np+1][0], bf[2*np+1][1], addrB);
            }
            #pragma unroll
            for (int m = 0; m < 4; m++) {
                uint32_t addrA = sA + stg + 4 * ((wm + m * 16) * 20 + kb);
                uint32_t a0, a1, a2, a3;
                ldsm4(a0, a1, a2, a3, addrA);
                #pragma unroll
                for (int nt = 0; nt < 8; nt++)
                    mma_f16(acc[m][nt], a0, a1, a2, a3, bf[nt][0], bf[nt][1]);
            }
        }

        if (t + 1 < 32) {
            if (t + 2 < 32) CPWAIT1(); else CPWAIT0();
            __syncthreads();
        }
    }

    // ---- epilogue ----
    #pragma unroll
    for (int nt = 0; nt < 8; nt++) {
        const int gc = col0 + wn + nt * 8 + tg * 2;
        const float b0 = bias[gc], b1 = bias[gc + 1];
        #pragma unroll
        for (int m = 0; m < 4; m++) {
            int r0 = row0 + wm + m * 16 + grp;
            int r1 = r0 + 8;
            float v00 = acc[m][nt][0] + b0, v01 = acc[m][nt][1] + b1;
            float v10 = acc[m][nt][2] + b0, v11 = acc[m][nt][3] + b1;
            if (outMode == 3) {
                float2 rr0 = *(const float2*)&resid[(size_t)r0 * DM_ + gc];
                float2 rr1 = *(const float2*)&resid[(size_t)r1 * DM_ + gc];
                float2 o0 = {v00 + rr0.x, v01 + rr0.y};
                float2 o1 = {v10 + rr1.x, v11 + rr1.y};
                *(float2*)&g_y[(size_t)r0 * DM_ + gc] = o0;
                *(float2*)&g_y[(size_t)r1 * DM_ + gc] = o1;
            } else if (outMode == 2) {
                const int hh = gc >> 6, d = gc & 63;
                const int b0i = r0 / L, k0i = r0 % L;
                const int b1i = r1 / L, k1i = r1 % L;
                size_t base0 = (size_t)(b0i * H_ + hh) * 64;
                size_t base1 = (size_t)(b1i * H_ + hh) * 64;
                g_vt[(base0 + d)     * LK_ + k0i] = __float2half(v00);
                g_vt[(base0 + d + 1) * LK_ + k0i] = __float2half(v01);
                g_vt[(base1 + d)     * LK_ + k1i] = __float2half(v10);
                g_vt[(base1 + d + 1) * LK_ + k1i] = __float2half(v11);
            } else {
                const int hh = gc >> 6, dp = (gc & 63) >> 1;
                const int b0i = r0 / L, ll0 = r0 % L;
                const int b1i = r1 / L, ll1 = r1 % L;
                uint32_t* oq = (outMode == 0) ? g_q : g_k;
                oq[((size_t)(b0i * H_ + hh) * L + ll0) * 32 + dp] = packh(v00, v01);
                oq[((size_t)(b1i * H_ + hh) * L + ll1) * 32 + dp] = packh(v10, v11);
            }
        }
    }
}

// ---------------------------------------------------------------------------
// fp16 flash attention v2: q-tile 128, warp = 32 q rows (2 m-slabs).
// 3-stage cp.async K/V/mask, 1 sync/tile, ldmatrix, Q fragments in regs.
// Block (128q, h, b), 128 thr (4 warps).
// ---------------------------------------------------------------------------
#define FQ (128 * 36)
#define F_STG (2 * 64 * 36 + 64)
#define FA_SMEM ((FQ + 3 * F_STG) * 4)

__global__ __launch_bounds__(128)
void flash_attn(const int* __restrict__ mask)
{
    extern __shared__ uint32_t sm[];
    uint32_t* Qs = sm;

    const int q0 = blockIdx.x * 128, h = blockIdx.y, b = blockIdx.z;
    const int tid  = threadIdx.x;
    const int lane = tid & 31;
    const int w    = tid >> 5;
    const int grp  = lane >> 2;
    const int tg   = lane & 3;

    const size_t bh_off = (size_t)(b * H_ + h);
    const uint32_t* kq_g = g_k + bh_off * LK_ * 32;
    const uint32_t* vt32 = (const uint32_t*)(g_vt + bh_off * 64 * LK_);
    const int* mk_g = mask + b * LK_;

    // ldmatrix B-type per-lane offsets (stride 36 layout)
    const int koff = ((lane >> 4) * 8 + (lane & 7)) * 36 + ((lane >> 3) & 1) * 4;
    const uint32_t sbase = smem_u32(sm);

    // K/V fill mapping: 2 threads per row of 32 u32
    const int kr = tid >> 1, kh = (tid & 1) * 16;
    auto fill = [&](int s, int k0) {
        uint32_t* Ks = sm + FQ + s * F_STG;
        uint32_t* Vs = Ks + 64 * 36;
        uint32_t* Ms = Vs + 64 * 36;
        #pragma unroll
        for (int i = 0; i < 4; i++) {
            CP16(smem_u32(&Ks[kr * 36 + kh + i * 4]),
                 &kq_g[(size_t)(k0 + kr) * 32 + kh + i * 4]);
            CP16(smem_u32(&Vs[kr * 36 + kh + i * 4]),
                 &vt32[(size_t)kr * (LK_ / 2) + (k0 >> 1) + kh + i * 4]);
        }
        if (tid < 16) CP16(smem_u32(&Ms[tid * 4]), &mk_g[k0 + tid * 4]);
        CPCOMMIT();
    };

    // ---- load Q tile (128 rows, 1 thread per row) ----
    {
        const uint32_t* qg = g_q + (bh_off * LQ_ + q0) * 32;
        #pragma unroll
        for (int i = 0; i < 8; i++)
            *(uint4*)&Qs[tid * 36 + i * 4] = *(const uint4*)&qg[(size_t)tid * 32 + i * 4];
    }
    fill(0, 0);
    fill(1, 64);
    CPWAIT1();
    __syncthreads();

    // ---- Q fragments (registers, whole mainloop): 2 m-slabs ----
    uint32_t qf[2][4][4];
    #pragma unroll
    for (int ms = 0; ms < 2; ms++) {
        const int r = w * 32 + ms * 16 + grp;
        #pragma unroll
        for (int kt = 0; kt < 4; kt++) {
            const int kb = kt * 8;
            qf[ms][kt][0] = Qs[r * 36 + kb + tg];
            qf[ms][kt][1] = Qs[(r + 8) * 36 + kb + tg];
            qf[ms][kt][2] = Qs[r * 36 + kb + tg + 4];
            qf[ms][kt][3] = Qs[(r + 8) * 36 + kb + tg + 4];
        }
    }

    float oacc[2][8][4];
    #pragma unroll
    for (int ms = 0; ms < 2; ms++)
        #pragma unroll
        for (int nt = 0; nt < 8; nt++)
            #pragma unroll
            for (int j = 0; j < 4; j++) oacc[ms][nt][j] = 0.f;
    float rm[2][2], rl[2][2];
    #pragma unroll
    for (int ms = 0; ms < 2; ms++) {
        rm[ms][0] = rm[ms][1] = -1e30f;
        rl[ms][0] = rl[ms][1] = 0.f;
    }

    const int NT = LK_ / 64;
    for (int t = 0; t < NT; t++) {
        if (t + 2 < NT) fill((t + 2) % 3, (t + 2) * 64);

        const uint32_t stq = (uint32_t)(FQ + (t % 3) * F_STG);
        const uint32_t sK = sbase + 4 * (stq + koff);
        const uint32_t sV = sK + 4 * (64 * 36);
        const int* mski = (const int*)(sm + stq + 2 * 64 * 36);

        // ---- S = Q K^T ----
        float s[2][8][4];
        #pragma unroll
        for (int ms = 0; ms < 2; ms++)
            #pragma unroll
            for (int nt = 0; nt < 8; nt++)
                #pragma unroll
                for (int j = 0; j < 4; j++) s[ms][nt][j] = 0.f;

        #pragma unroll
        for (int kt = 0; kt < 4; kt++) {
            const int kb = kt * 8;
            #pragma unroll
            for (int np = 0; np < 4; np++) {
                uint32_t b0, b1, b2, b3;
                ldsm4(b0, b1, b2, b3, sK + 4 * (np * 16 * 36 + kb));
                #pragma unroll
                for (int ms = 0; ms < 2; ms++) {
                    mma_f16(s[ms][2*np],   qf[ms][kt][0], qf[ms][kt][1], qf[ms][kt][2], qf[ms][kt][3], b0, b1);
                    mma_f16(s[ms][2*np+1], qf[ms][kt][0], qf[ms][kt][1], qf[ms][kt][2], qf[ms][kt][3], b2, b3);
                }
            }
        }

        // ---- online softmax (mask shared across m-slabs) ----
        const float scl = 0.125f;
        float mk[8][2];
        #pragma unroll
        for (int nt = 0; nt < 8; nt++) {
            mk[nt][0] = (mski[nt * 8 + 2 * tg]     == 0) ? -1e30f : 0.0f;
            mk[nt][1] = (mski[nt * 8 + 2 * tg + 1] == 0) ? -1e30f : 0.0f;
        }

        #pragma unroll
        for (int ms = 0; ms < 2; ms++) {
            float rmax0 = -1e30f, rmax1 = -1e30f;
            #pragma unroll
            for (int nt = 0; nt < 8; nt++) {
                s[ms][nt][0] = s[ms][nt][0] * scl + mk[nt][0];
                s[ms][nt][1] = s[ms][nt][1] * scl + mk[nt][1];
                s[ms][nt][2] = s[ms][nt][2] * scl + mk[nt][0];
                s[ms][nt][3] = s[ms][nt][3] * scl + mk[nt][1];
                rmax0 = fmaxf(rmax0, fmaxf(s[ms][nt][0], s[ms][nt][1]));
                rmax1 = fmaxf(rmax1, fmaxf(s[ms][nt][2], s[ms][nt][3]));
            }
            rmax0 = fmaxf(rmax0, __shfl_xor_sync(0xffffffffu, rmax0, 1));
            rmax0 = fmaxf(rmax0, __shfl_xor_sync(0xffffffffu, rmax0, 2));
            rmax1 = fmaxf(rmax1, __shfl_xor_sync(0xffffffffu, rmax1, 1));
            rmax1 = fmaxf(rmax1, __shfl_xor_sync(0xffffffffu, rmax1, 2));

            float mn0 = fmaxf(rm[ms][0], rmax0), mn1 = fmaxf(rm[ms][1], rmax1);
            float c0 = __expf(rm[ms][0] - mn0),  c1 = __expf(rm[ms][1] - mn1);
            rm[ms][0] = mn0; rm[ms][1] = mn1;

            float sum0 = 0.f, sum1 = 0.f;
            #pragma unroll
            for (int nt = 0; nt < 8; nt++) {
                s[ms][nt][0] = __expf(s[ms][nt][0] - mn0);
                s[ms][nt][1] = __expf(s[ms][nt][1] - mn0);
                s[ms][nt][2] = __expf(s[ms][nt][2] - mn1);
                s[ms][nt][3] = __expf(s[ms][nt][3] - mn1);
                sum0 += s[ms][nt][0] + s[ms][nt][1];
                sum1 += s[ms][nt][2] + s[ms][nt][3];
            }
            sum0 += __shfl_xor_sync(0xffffffffu, sum0, 1);
            sum0 += __shfl_xor_sync(0xffffffffu, sum0, 2);
            sum1 += __shfl_xor_sync(0xffffffffu, sum1, 1);
            sum1 += __shfl_xor_sync(0xffffffffu, sum1, 2);
            rl[ms][0] = rl[ms][0] * c0 + sum0;
            rl[ms][1] = rl[ms][1] * c1 + sum1;

            #pragma unroll
            for (int nt = 0; nt < 8; nt++) {
                oacc[ms][nt][0] *= c0; oacc[ms][nt][1] *= c0;
                oacc[ms][nt][2] *= c1; oacc[ms][nt][3] *= c1;
            }
        }

        // ---- O += P V ----
        #pragma unroll
        for (int kg = 0; kg < 4; kg++) {
            uint32_t pa[2][4];
            #pragma unroll
            for (int ms = 0; ms < 2; ms++) {
                pa[ms][0] = packh(s[ms][2*kg][0],   s[ms][2*kg][1]);
                pa[ms][1] = packh(s[ms][2*kg][2],   s[ms][2*kg][3]);
                pa[ms][2] = packh(s[ms][2*kg+1][0], s[ms][2*kg+1][1]);
                pa[ms][3] = packh(s[ms][2*kg+1][2], s[ms][2*kg+1][3]);
            }
            const int kb = kg * 8;
            #pragma unroll
            for (int np = 0; np < 4; np++) {
                uint32_t b0, b1, b2, b3;
                ldsm4(b0, b1, b2, b3, sV + 4 * (np * 16 * 36 + kb));
                #pragma unroll
                for (int ms = 0; ms < 2; ms++) {
                    mma_f16(oacc[ms][2*np],   pa[ms][0], pa[ms][1], pa[ms][2], pa[ms][3], b0, b1);
                    mma_f16(oacc[ms][2*np+1], pa[ms][0], pa[ms][1], pa[ms][2], pa[ms][3], b2, b3);
                }
            }
        }

        if (t + 1 < NT) {
            if (t + 2 < NT) CPWAIT1(); else CPWAIT0();
            __syncthreads();
        }
    }

    // ---- epilogue: packed fp16 attention output ----
    #pragma unroll
    for (int ms = 0; ms < 2; ms++) {
        float inv0 = 1.0f / rl[ms][0], inv1 = 1.0f / rl[ms][1];
        int qr0 = q0 + w * 32 + ms * 16 + grp;
        int qr1 = qr0 + 8;
        size_t r0base = ((size_t)b * LQ_ + qr0) * 512 + h * 32;
        size_t r1base = ((size_t)b * LQ_ + qr1) * 512 + h * 32;
        #pragma unroll
        for (int nt = 0; nt < 8; nt++) {
            int dp = nt * 4 + tg;
            g_ao[r0base + dp] = packh(oacc[ms][nt][0] * inv0, oacc[ms][nt][1] * inv0);
            g_ao[r1base + dp] = packh(oacc[ms][nt][2] * inv1, oacc[ms][nt][3] * inv1);
        }
    }
}

// ---------------------------------------------------------------------------
// LayerNorm per row of g_y
// ---------------------------------------------------------------------------
__global__ void layernorm_kernel(const float* __restrict__ gamma,
                                 const float* __restrict__ beta,
                                 float* __restrict__ out)
{
    const int row = blockIdx.x;
    const int tid = threadIdx.x;
    __shared__ float red[256];

    const float* yr = g_y + (size_t)row * DM_;
    float4 xv = *(const float4*)(yr + tid * 4);

    float s = xv.x + xv.y + xv.z + xv.w;
    red[tid] = s; __syncthreads();
    #pragma unroll
    for (int st = 128; st > 0; st >>= 1) {
        if (tid < st) red[tid] += red[tid + st];
        __syncthreads();
    }
    float mean = red[0] * (1.0f / DM_);
    __syncthreads();

    float dx = xv.x - mean, dy = xv.y - mean, dz = xv.z - mean, dw = xv.w - mean;
    float sq = dx * dx + dy * dy + dz * dz + dw * dw;
    red[tid] = sq; __syncthreads();
    #pragma unroll
    for (int st = 128; st > 0; st >>= 1) {
        if (tid < st) red[tid] += red[tid + st];
        __syncthreads();
    }
    float rstd = rsqrtf(red[0] * (1.0f / DM_) + 1e-5f);

    int n = tid * 4;
    float4 ov;
    ov.x = dx * rstd * gamma[n]     + beta[n];
    ov.y = dy * rstd * gamma[n + 1] + beta[n + 1];
    ov.z = dz * rstd * gamma[n + 2] + beta[n + 2];
    ov.w = dw * rstd * gamma[n + 3] + beta[n + 3];
    *(float4*)(out + (size_t)row * DM_ + n) = ov;
}

// ---------------------------------------------------------------------------
extern "C" void kernel_launch(void* const* d_in, const int* in_sizes, int n_in,
                              void* d_out, int out_size)
{
    const float* Q    = (const float*)d_in[0];
    const float* K    = (const float*)d_in[1];
    const float* V    = (const float*)d_in[2];
    /* d_in[3] = node_num (unused) */
    const int*   mask = (const int*)  d_in[4];
    const float* Wq   = (const float*)d_in[5];
    const float* bq   = (const float*)d_in[6];
    const float* Wk   = (const float*)d_in[7];
    const float* bk   = (const float*)d_in[8];
    const float* Wv   = (const float*)d_in[9];
    const float* bv   = (const float*)d_in[10];
    const float* Wo   = (const float*)d_in[11];
    const float* bo   = (const float*)d_in[12];
    const float* gamma= (const float*)d_in[13];
    const float* beta = (const float*)d_in[14];
    float* out = (float*)d_out;

    cudaFuncSetAttribute(gemm_h,     cudaFuncAttributeMaxDynamicSharedMemorySize, GEMM_SMEM);
    cudaFuncSetAttribute(flash_attn, cudaFuncAttributeMaxDynamicSharedMemorySize, FA_SMEM);

    __half *wt, *x;
    uint32_t *ao;
    cudaGetSymbolAddress((void**)&wt, g_wt);
    cudaGetSymbolAddress((void**)&x,  g_x);
    cudaGetSymbolAddress((void**)&ao, g_ao);

    const size_t WS = (size_t)DM_ * DM_;

    // ---- pre-pass conversions (2 launches) ----
    convert_wt_all<<<dim3(16, 16, 4), 256>>>(Wq, Wk, Wv, Wo, wt);
    convert_x_all<<<18432, 256>>>(Q, K, V, x);

    // ---- Q projection ----
    gemm_h<<<dim3(8, 16, 1), 128, GEMM_SMEM>>>(
        x + (size_t)XQ_ROW * DM_, x + (size_t)XQ_ROW * DM_,
        wt + 0 * WS, wt + 0 * WS, bq, bq, nullptr, LQ_, 0, 0);

    // ---- K + V projections (merged launch, z selects) ----
    gemm_h<<<dim3(8, 64, 2), 128, GEMM_SMEM>>>(
        x + (size_t)XK_ROW * DM_, x + (size_t)XV_ROW * DM_,
        wt + 1 * WS, wt + 2 * WS, bk, bv, nullptr, LK_, 1, 2);

    // ---- attention (128-q tiles) ----
    flash_attn<<<dim3(LQ_ / 128, H_, B_), 128, FA_SMEM>>>(mask);

    // ---- output projection + residual ----
    gemm_h<<<dim3(8, 16, 1), 128, GEMM_SMEM>>>(
        (const __half*)ao, (const __half*)ao,
        wt + 3 * WS, wt + 3 * WS, bo, bo, Q, LQ_, 3, 3);

    // ---- layernorm ----
    layernorm_kernel<<<B_ * LQ_, 256>>>(gamma, beta, out);
}

// round 15
// speedup vs baseline: 1.6013x; 1.2447x over previous
#include <cuda_runtime.h>
#include <cuda_fp16.h>
#include <math.h>
#include <stdint.h>

#define B_  4
#define H_  16
#define LQ_ 512
#define LK_ 2048
#define DM_ 1024

#define XQ_ROW 0
#define XK_ROW 2048
#define XV_ROW (2048 + 8192)

// ---------------------------------------------------------------------------
// Scratch (device globals; no runtime allocation allowed)
// ---------------------------------------------------------------------------
__device__ __align__(16) __half    g_wt [(size_t)4 * DM_ * DM_];     // W^T [mat][n][k] fp16
__device__ __align__(16) __half    g_x  [(size_t)18432 * DM_];       // X fp16 [row][k]
__device__ __align__(16) uint32_t  g_q  [(size_t)B_*H_*LQ_*32];      // q [b,h,l,dpair] half2
__device__ __align__(16) uint32_t  g_k  [(size_t)B_*H_*LK_*32];      // k [b,h,l,dpair] half2
__device__ __align__(16) __half    g_vt [(size_t)B_*H_*64*LK_];      // V^T [b,h,d,key] fp16
__device__ __align__(16) uint32_t  g_ao [(size_t)B_*LQ_*512];        // attn out [row][dpair] half2
__device__ __align__(16) float     g_y  [(size_t)B_*LQ_*DM_];        // O-proj partial (k 0..511)
__device__ __align__(16) float     g_y2 [(size_t)B_*LQ_*DM_];        // O-proj partial (k 512..1023)

// ---------------------------------------------------------------------------
// helpers
// ---------------------------------------------------------------------------
__device__ __forceinline__ uint32_t packh(float e, float o) {
    uint32_t r;
    asm("cvt.rn.f16x2.f32 %0, %1, %2;" : "=r"(r) : "f"(o), "f"(e));
    return r;
}

__device__ __forceinline__ void mma_f16(float c[4],
                                        uint32_t a0, uint32_t a1, uint32_t a2, uint32_t a3,
                                        uint32_t b0, uint32_t b1)
{
    asm volatile(
        "mma.sync.aligned.m16n8k16.row.col.f32.f16.f16.f32 "
        "{%0,%1,%2,%3}, {%4,%5,%6,%7}, {%8,%9}, {%0,%1,%2,%3};"
        : "+f"(c[0]), "+f"(c[1]), "+f"(c[2]), "+f"(c[3])
        : "r"(a0), "r"(a1), "r"(a2), "r"(a3), "r"(b0), "r"(b1));
}

__device__ __forceinline__ void ldsm4(uint32_t& r0, uint32_t& r1, uint32_t& r2, uint32_t& r3,
                                      uint32_t addr)
{
    asm volatile("ldmatrix.sync.aligned.m8n8.x4.shared.b16 {%0,%1,%2,%3}, [%4];"
                 : "=r"(r0), "=r"(r1), "=r"(r2), "=r"(r3) : "r"(addr));
}

__device__ __forceinline__ uint32_t smem_u32(const void* p) {
    uint32_t a;
    asm("{ .reg .u64 t; cvta.to.shared.u64 t, %1; cvt.u32.u64 %0, t; }" : "=r"(a) : "l"(p));
    return a;
}

#define CP16(dst, src) \
    asm volatile("cp.async.cg.shared.global [%0], [%1], 16;" :: "r"(dst), "l"(src) : "memory")
#define CPCOMMIT() asm volatile("cp.async.commit_group;" ::: "memory")
#define CPWAIT1()  asm volatile("cp.async.wait_group 1;" ::: "memory")
#define CPWAIT0()  asm volatile("cp.async.wait_group 0;" ::: "memory")

// ---------------------------------------------------------------------------
// Pre-pass: all X fp32 -> fp16
// ---------------------------------------------------------------------------
__global__ void convert_x_all(const float* __restrict__ Q, const float* __restrict__ K,
                              const float* __restrict__ V, __half* __restrict__ dst)
{
    const int row = blockIdx.x;
    const float* src;
    int lr;
    if (row < 2048)       { src = Q; lr = row; }
    else if (row < 10240) { src = K; lr = row - 2048; }
    else                  { src = V; lr = row - 10240; }
    float4 v = ((const float4*)(src + (size_t)lr * DM_))[threadIdx.x];
    uint2 p;
    p.x = packh(v.x, v.y);
    p.y = packh(v.z, v.w);
    ((uint2*)(dst + (size_t)row * DM_))[threadIdx.x] = p;
}

// Pre-pass: all W [k][n] fp32 -> W^T [n][k] fp16 (z = matrix)
__global__ void convert_wt_all(const float* __restrict__ W0, const float* __restrict__ W1,
                               const float* __restrict__ W2, const float* __restrict__ W3,
                               __half* __restrict__ T)
{
    __shared__ float tile[64][65];
    const int z = blockIdx.z;
    const float* W = (z == 0) ? W0 : (z == 1) ? W1 : (z == 2) ? W2 : W3;
    __half* Tz = T + (size_t)z * DM_ * DM_;
    const int n0 = blockIdx.x * 64, k0 = blockIdx.y * 64;
    const int tid = threadIdx.x;
    #pragma unroll
    for (int i = 0; i < 16; i++) {
        int idx = tid + i * 256;
        int r = idx >> 6, c = idx & 63;
        tile[r][c] = W[(size_t)(k0 + r) * DM_ + n0 + c];
    }
    __syncthreads();
    #pragma unroll
    for (int i = 0; i < 16; i++) {
        int idx = tid + i * 256;
        int nr = idx >> 6, kc = idx & 63;
        Tz[(size_t)(n0 + nr) * DM_ + k0 + kc] = __float2half(tile[kc][nr]);
    }
}

// ---------------------------------------------------------------------------
// Core fp16 GEMM body (R13 mainloop): CTA 128x128, 128 thr, warp 64x64,
// 3-stage cp.async, 1 sync/tile, ldmatrix. Parametrized k-tile range.
// ---------------------------------------------------------------------------
#define G_STG (2 * 128 * 20)
#define GEMM_SMEM (3 * G_STG * 4)

struct GemmCtx {
    const uint32_t* a32;    // A rows base (u32 = half2), row stride 512
    const uint32_t* b32;    // B rows base
    int arow0;              // A row of this CTA tile
    int col0;               // B row / output col
    int kt0, nkt;           // k-tile range
};

__device__ __forceinline__ void gemm_core(const GemmCtx& c, uint32_t* sm,
                                          float acc[4][8][4])
{
    const int tid  = threadIdx.x;
    const int lane = tid & 31;
    const int w    = tid >> 5;
    const int wm   = (w >> 1) * 64;
    const int wn   = (w & 1) * 64;

    const int aoff = (((lane >> 3) & 1) * 8 + (lane & 7)) * 20 + (lane >> 4) * 4;
    const int boff = ((lane >> 4) * 8 + (lane & 7)) * 20 + ((lane >> 3) & 1) * 4;

    const uint32_t sbase = smem_u32(sm);
    const uint32_t sA = sbase + 4 * aoff;
    const uint32_t sB = sbase + 4 * (128 * 20 + boff);

    const int fr = tid >> 2;
    const int fc = tid & 3;
    auto fill = [&](int s, int tt) {
        const int kp0 = (c.kt0 + tt) * 16;
        uint32_t* As = sm + s * G_STG;
        uint32_t* Bs = As + 128 * 20;
        #pragma unroll
        for (int i = 0; i < 4; i++) {
            int r = fr + i * 32;
            CP16(smem_u32(&As[r * 20 + fc * 4]), &c.a32[(size_t)(c.arow0 + r) * 512 + kp0 + fc * 4]);
            CP16(smem_u32(&Bs[r * 20 + fc * 4]), &c.b32[(size_t)(c.col0 + r) * 512 + kp0 + fc * 4]);
        }
        CPCOMMIT();
    };

    fill(0, 0);
    fill(1, 1);
    CPWAIT1();
    __syncthreads();

    for (int t = 0; t < c.nkt; t++) {
        if (t + 2 < c.nkt) fill((t + 2) % 3, t + 2);

        const uint32_t stg = (uint32_t)((t % 3) * (G_STG * 4));
        #pragma unroll
        for (int kt = 0; kt < 2; kt++) {
            const int kb = kt * 8;
            uint32_t bf[8][2];
            #pragma unroll
            for (int np = 0; np < 4; np++) {
                uint32_t addrB = sB + stg + 4 * ((wn + np * 16) * 20 + kb);
                ldsm4(bf[2*np][0], bf[2*np][1], bf[2*np+1][0], bf[2*np+1][1], addrB);
            }
            #pragma unroll
            for (int m = 0; m < 4; m++) {
                uint32_t addrA = sA + stg + 4 * ((wm + m * 16) * 20 + kb);
                uint32_t a0, a1, a2, a3;
                ldsm4(a0, a1, a2, a3, addrA);
                #pragma unroll
                for (int nt = 0; nt < 8; nt++)
                    mma_f16(acc[m][nt], a0, a1, a2, a3, bf[nt][0], bf[nt][1]);
            }
        }

        if (t + 1 < c.nkt) {
            if (t + 2 < c.nkt) CPWAIT1(); else CPWAIT0();
            __syncthreads();
        }
    }
}

// ---------------------------------------------------------------------------
// Merged Q/K/V projection launch: grid (8, 144).
// y in [0,16): Q-proj; [16,80): K-proj; [80,144): V-proj.
// ---------------------------------------------------------------------------
__global__ __launch_bounds__(128)
void gemm_qkv(const __half* __restrict__ X, const __half* __restrict__ WT,
              const float* __restrict__ bq, const float* __restrict__ bk,
              const float* __restrict__ bv)
{
    extern __shared__ uint32_t sm[];
    const int y = blockIdx.y;

    int seg, ybase, L, outMode, xrow;
    const float* bias;
    if (y < 16)      { seg = 0; ybase = 0;  L = LQ_; outMode = 0; xrow = XQ_ROW; bias = bq; }
    else if (y < 80) { seg = 1; ybase = 16; L = LK_; outMode = 1; xrow = XK_ROW; bias = bk; }
    else             { seg = 2; ybase = 80; L = LK_; outMode = 2; xrow = XV_ROW; bias = bv; }

    const int lrow0 = (y - ybase) * 128;      // row within segment
    const int col0  = blockIdx.x * 128;

    GemmCtx c;
    c.a32   = (const uint32_t*)(g_x + (size_t)xrow * DM_);
    c.b32   = (const uint32_t*)(WT + (size_t)seg * DM_ * DM_);
    c.arow0 = lrow0;
    c.col0  = col0;
    c.kt0   = 0;
    c.nkt   = 32;

    float acc[4][8][4] = {};
    gemm_core(c, sm, acc);

    const int lane = threadIdx.x & 31;
    const int w    = threadIdx.x >> 5;
    const int wm   = (w >> 1) * 64;
    const int wn   = (w & 1) * 64;
    const int grp  = lane >> 2;
    const int tg   = lane & 3;

    #pragma unroll
    for (int nt = 0; nt < 8; nt++) {
        const int gc = col0 + wn + nt * 8 + tg * 2;
        const float b0 = bias[gc], b1 = bias[gc + 1];
        #pragma unroll
        for (int m = 0; m < 4; m++) {
            int r0 = lrow0 + wm + m * 16 + grp;
            int r1 = r0 + 8;
            float v00 = acc[m][nt][0] + b0, v01 = acc[m][nt][1] + b1;
            float v10 = acc[m][nt][2] + b0, v11 = acc[m][nt][3] + b1;
            const int hh = gc >> 6;
            const int b0i = r0 / L, l0i = r0 % L;
            const int b1i = r1 / L, l1i = r1 % L;
            if (outMode == 2) {
                const int d = gc & 63;
                size_t base0 = (size_t)(b0i * H_ + hh) * 64;
                size_t base1 = (size_t)(b1i * H_ + hh) * 64;
                g_vt[(base0 + d)     * LK_ + l0i] = __float2half(v00);
                g_vt[(base0 + d + 1) * LK_ + l0i] = __float2half(v01);
                g_vt[(base1 + d)     * LK_ + l1i] = __float2half(v10);
                g_vt[(base1 + d + 1) * LK_ + l1i] = __float2half(v11);
            } else {
                const int dp = (gc & 63) >> 1;
                uint32_t* oq = (outMode == 0) ? g_q : g_k;
                oq[((size_t)(b0i * H_ + hh) * L + l0i) * 32 + dp] = packh(v00, v01);
                oq[((size_t)(b1i * H_ + hh) * L + l1i) * 32 + dp] = packh(v10, v11);
            }
        }
    }
}

// ---------------------------------------------------------------------------
// O-projection split-K x2: grid (8, 16, 2). z = k-half. Writes raw partials.
// ---------------------------------------------------------------------------
__global__ __launch_bounds__(128)
void gemm_o(const __half* __restrict__ WT)
{
    extern __shared__ uint32_t sm[];
    const int z = blockIdx.z;
    const int row0 = blockIdx.y * 128;
    const int col0 = blockIdx.x * 128;

    GemmCtx c;
    c.a32   = (const uint32_t*)g_ao;
    c.b32   = (const uint32_t*)(WT + (size_t)3 * DM_ * DM_);
    c.arow0 = row0;
    c.col0  = col0;
    c.kt0   = z * 16;
    c.nkt   = 16;

    float acc[4][8][4] = {};
    gemm_core(c, sm, acc);

    const int lane = threadIdx.x & 31;
    const int w    = threadIdx.x >> 5;
    const int wm   = (w >> 1) * 64;
    const int wn   = (w & 1) * 64;
    const int grp  = lane >> 2;
    const int tg   = lane & 3;

    float* dst = z ? g_y2 : g_y;
    #pragma unroll
    for (int nt = 0; nt < 8; nt++) {
        const int gc = col0 + wn + nt * 8 + tg * 2;
        #pragma unroll
        for (int m = 0; m < 4; m++) {
            int r0 = row0 + wm + m * 16 + grp;
            int r1 = r0 + 8;
            float2 o0 = {acc[m][nt][0], acc[m][nt][1]};
            float2 o1 = {acc[m][nt][2], acc[m][nt][3]};
            *(float2*)&dst[(size_t)r0 * DM_ + gc] = o0;
            *(float2*)&dst[(size_t)r1 * DM_ + gc] = o1;
        }
    }
}

// ---------------------------------------------------------------------------
// fp16 flash attention (R14, unchanged): q-tile 128, warp = 32 q rows.
// ---------------------------------------------------------------------------
#define FQ (128 * 36)
#define F_STG (2 * 64 * 36 + 64)
#define FA_SMEM ((FQ + 3 * F_STG) * 4)

__global__ __launch_bounds__(128)
void flash_attn(const int* __restrict__ mask)
{
    extern __shared__ uint32_t sm[];
    uint32_t* Qs = sm;

    const int q0 = blockIdx.x * 128, h = blockIdx.y, b = blockIdx.z;
    const int tid  = threadIdx.x;
    const int lane = tid & 31;
    const int w    = tid >> 5;
    const int grp  = lane >> 2;
    const int tg   = lane & 3;

    const size_t bh_off = (size_t)(b * H_ + h);
    const uint32_t* kq_g = g_k + bh_off * LK_ * 32;
    const uint32_t* vt32 = (const uint32_t*)(g_vt + bh_off * 64 * LK_);
    const int* mk_g = mask + b * LK_;

    const int koff = ((lane >> 4) * 8 + (lane & 7)) * 36 + ((lane >> 3) & 1) * 4;
    const uint32_t sbase = smem_u32(sm);

    const int kr = tid >> 1, kh = (tid & 1) * 16;
    auto fill = [&](int s, int k0) {
        uint32_t* Ks = sm + FQ + s * F_STG;
        uint32_t* Vs = Ks + 64 * 36;
        uint32_t* Ms = Vs + 64 * 36;
        #pragma unroll
        for (int i = 0; i < 4; i++) {
            CP16(smem_u32(&Ks[kr * 36 + kh + i * 4]),
                 &kq_g[(size_t)(k0 + kr) * 32 + kh + i * 4]);
            CP16(smem_u32(&Vs[kr * 36 + kh + i * 4]),
                 &vt32[(size_t)kr * (LK_ / 2) + (k0 >> 1) + kh + i * 4]);
        }
        if (tid < 16) CP16(smem_u32(&Ms[tid * 4]), &mk_g[k0 + tid * 4]);
        CPCOMMIT();
    };

    {
        const uint32_t* qg = g_q + (bh_off * LQ_ + q0) * 32;
        #pragma unroll
        for (int i = 0; i < 8; i++)
            *(uint4*)&Qs[tid * 36 + i * 4] = *(const uint4*)&qg[(size_t)tid * 32 + i * 4];
    }
    fill(0, 0);
    fill(1, 64);
    CPWAIT1();
    __syncthreads();

    uint32_t qf[2][4][4];
    #pragma unroll
    for (int ms = 0; ms < 2; ms++) {
        const int r = w * 32 + ms * 16 + grp;
        #pragma unroll
        for (int kt = 0; kt < 4; kt++) {
            const int kb = kt * 8;
            qf[ms][kt][0] = Qs[r * 36 + kb + tg];
            qf[ms][kt][1] = Qs[(r + 8) * 36 + kb + tg];
            qf[ms][kt][2] = Qs[r * 36 + kb + tg + 4];
            qf[ms][kt][3] = Qs[(r + 8) * 36 + kb + tg + 4];
        }
    }

    float oacc[2][8][4];
    #pragma unroll
    for (int ms = 0; ms < 2; ms++)
        #pragma unroll
        for (int nt = 0; nt < 8; nt++)
            #pragma unroll
            for (int j = 0; j < 4; j++) oacc[ms][nt][j] = 0.f;
    float rm[2][2], rl[2][2];
    #pragma unroll
    for (int ms = 0; ms < 2; ms++) {
        rm[ms][0] = rm[ms][1] = -1e30f;
        rl[ms][0] = rl[ms][1] = 0.f;
    }

    const int NT = LK_ / 64;
    for (int t = 0; t < NT; t++) {
        if (t + 2 < NT) fill((t + 2) % 3, (t + 2) * 64);

        const uint32_t stq = (uint32_t)(FQ + (t % 3) * F_STG);
        const uint32_t sK = sbase + 4 * (stq + koff);
        const uint32_t sV = sK + 4 * (64 * 36);
        const int* mski = (const int*)(sm + stq + 2 * 64 * 36);

        float s[2][8][4];
        #pragma unroll
        for (int ms = 0; ms < 2; ms++)
            #pragma unroll
            for (int nt = 0; nt < 8; nt++)
                #pragma unroll
                for (int j = 0; j < 4; j++) s[ms][nt][j] = 0.f;

        #pragma unroll
        for (int kt = 0; kt < 4; kt++) {
            const int kb = kt * 8;
            #pragma unroll
            for (int np = 0; np < 4; np++) {
                uint32_t b0, b1, b2, b3;
                ldsm4(b0, b1, b2, b3, sK + 4 * (np * 16 * 36 + kb));
                #pragma unroll
                for (int ms = 0; ms < 2; ms++) {
                    mma_f16(s[ms][2*np],   qf[ms][kt][0], qf[ms][kt][1], qf[ms][kt][2], qf[ms][kt][3], b0, b1);
                    mma_f16(s[ms][2*np+1], qf[ms][kt][0], qf[ms][kt][1], qf[ms][kt][2], qf[ms][kt][3], b2, b3);
                }
            }
        }

        const float scl = 0.125f;
        float mk[8][2];
        #pragma unroll
        for (int nt = 0; nt < 8; nt++) {
            mk[nt][0] = (mski[nt * 8 + 2 * tg]     == 0) ? -1e30f : 0.0f;
            mk[nt][1] = (mski[nt * 8 + 2 * tg + 1] == 0) ? -1e30f : 0.0f;
        }

        #pragma unroll
        for (int ms = 0; ms < 2; ms++) {
            float rmax0 = -1e30f, rmax1 = -1e30f;
            #pragma unroll
            for (int nt = 0; nt < 8; nt++) {
                s[ms][nt][0] = s[ms][nt][0] * scl + mk[nt][0];
                s[ms][nt][1] = s[ms][nt][1] * scl + mk[nt][1];
                s[ms][nt][2] = s[ms][nt][2] * scl + mk[nt][0];
                s[ms][nt][3] = s[ms][nt][3] * scl + mk[nt][1];
                rmax0 = fmaxf(rmax0, fmaxf(s[ms][nt][0], s[ms][nt][1]));
                rmax1 = fmaxf(rmax1, fmaxf(s[ms][nt][2], s[ms][nt][3]));
            }
            rmax0 = fmaxf(rmax0, __shfl_xor_sync(0xffffffffu, rmax0, 1));
            rmax0 = fmaxf(rmax0, __shfl_xor_sync(0xffffffffu, rmax0, 2));
            rmax1 = fmaxf(rmax1, __shfl_xor_sync(0xffffffffu, rmax1, 1));
            rmax1 = fmaxf(rmax1, __shfl_xor_sync(0xffffffffu, rmax1, 2));

            float mn0 = fmaxf(rm[ms][0], rmax0), mn1 = fmaxf(rm[ms][1], rmax1);
            float c0 = __expf(rm[ms][0] - mn0),  c1 = __expf(rm[ms][1] - mn1);
            rm[ms][0] = mn0; rm[ms][1] = mn1;

            float sum0 = 0.f, sum1 = 0.f;
            #pragma unroll
            for (int nt = 0; nt < 8; nt++) {
                s[ms][nt][0] = __expf(s[ms][nt][0] - mn0);
                s[ms][nt][1] = __expf(s[ms][nt][1] - mn0);
                s[ms][nt][2] = __expf(s[ms][nt][2] - mn1);
                s[ms][nt][3] = __expf(s[ms][nt][3] - mn1);
                sum0 += s[ms][nt][0] + s[ms][nt][1];
                sum1 += s[ms][nt][2] + s[ms][nt][3];
            }
            sum0 += __shfl_xor_sync(0xffffffffu, sum0, 1);
            sum0 += __shfl_xor_sync(0xffffffffu, sum0, 2);
            sum1 += __shfl_xor_sync(0xffffffffu, sum1, 1);
            sum1 += __shfl_xor_sync(0xffffffffu, sum1, 2);
            rl[ms][0] = rl[ms][0] * c0 + sum0;
            rl[ms][1] = rl[ms][1] * c1 + sum1;

            #pragma unroll
            for (int nt = 0; nt < 8; nt++) {
                oacc[ms][nt][0] *= c0; oacc[ms][nt][1] *= c0;
                oacc[ms][nt][2] *= c1; oacc[ms][nt][3] *= c1;
            }
        }

        #pragma unroll
        for (int kg = 0; kg < 4; kg++) {
            uint32_t pa[2][4];
            #pragma unroll
            for (int ms = 0; ms < 2; ms++) {
                pa[ms][0] = packh(s[ms][2*kg][0],   s[ms][2*kg][1]);
                pa[ms][1] = packh(s[ms][2*kg][2],   s[ms][2*kg][3]);
                pa[ms][2] = packh(s[ms][2*kg+1][0], s[ms][2*kg+1][1]);
                pa[ms][3] = packh(s[ms][2*kg+1][2], s[ms][2*kg+1][3]);
            }
            const int kb = kg * 8;
            #pragma unroll
            for (int np = 0; np < 4; np++) {
                uint32_t b0, b1, b2, b3;
                ldsm4(b0, b1, b2, b3, sV + 4 * (np * 16 * 36 + kb));
                #pragma unroll
                for (int ms = 0; ms < 2; ms++) {
                    mma_f16(oacc[ms][2*np],   pa[ms][0], pa[ms][1], pa[ms][2], pa[ms][3], b0, b1);
                    mma_f16(oacc[ms][2*np+1], pa[ms][0], pa[ms][1], pa[ms][2], pa[ms][3], b2, b3);
                }
            }
        }

        if (t + 1 < NT) {
            if (t + 2 < NT) CPWAIT1(); else CPWAIT0();
            __syncthreads();
        }
    }

    #pragma unroll
    for (int ms = 0; ms < 2; ms++) {
        float inv0 = 1.0f / rl[ms][0], inv1 = 1.0f / rl[ms][1];
        int qr0 = q0 + w * 32 + ms * 16 + grp;
        int qr1 = qr0 + 8;
        size_t r0base = ((size_t)b * LQ_ + qr0) * 512 + h * 32;
        size_t r1base = ((size_t)b * LQ_ + qr1) * 512 + h * 32;
        #pragma unroll
        for (int nt = 0; nt < 8; nt++) {
            int dp = nt * 4 + tg;
            g_ao[r0base + dp] = packh(oacc[ms][nt][0] * inv0, oacc[ms][nt][1] * inv0);
            g_ao[r1base + dp] = packh(oacc[ms][nt][2] * inv1, oacc[ms][nt][3] * inv1);
        }
    }
}

// ---------------------------------------------------------------------------
// LayerNorm: sum split-K partials + bias + residual, then normalize.
// ---------------------------------------------------------------------------
__global__ void layernorm_kernel(const float* __restrict__ gamma,
                                 const float* __restrict__ beta,
                                 const float* __restrict__ bo,
                                 const float* __restrict__ resid,
                                 float* __restrict__ out)
{
    const int row = blockIdx.x;
    const int tid = threadIdx.x;
    __shared__ float red[256];

    const int n = tid * 4;
    float4 y0 = *(const float4*)(g_y  + (size_t)row * DM_ + n);
    float4 y1 = *(const float4*)(g_y2 + (size_t)row * DM_ + n);
    float4 bb = *(const float4*)(bo + n);
    float4 rr = *(const float4*)(resid + (size_t)row * DM_ + n);
    float4 xv;
    xv.x = y0.x + y1.x + bb.x + rr.x;
    xv.y = y0.y + y1.y + bb.y + rr.y;
    xv.z = y0.z + y1.z + bb.z + rr.z;
    xv.w = y0.w + y1.w + bb.w + rr.w;

    float s = xv.x + xv.y + xv.z + xv.w;
    red[tid] = s; __syncthreads();
    #pragma unroll
    for (int st = 128; st > 0; st >>= 1) {
        if (tid < st) red[tid] += red[tid + st];
        __syncthreads();
    }
    float mean = red[0] * (1.0f / DM_);
    __syncthreads();

    float dx = xv.x - mean, dy = xv.y - mean, dz = xv.z - mean, dw = xv.w - mean;
    float sq = dx * dx + dy * dy + dz * dz + dw * dw;
    red[tid] = sq; __syncthreads();
    #pragma unroll
    for (int st = 128; st > 0; st >>= 1) {
        if (tid < st) red[tid] += red[tid + st];
        __syncthreads();
    }
    float rstd = rsqrtf(red[0] * (1.0f / DM_) + 1e-5f);

    float4 ov;
    ov.x = dx * rstd * gamma[n]     + beta[n];
    ov.y = dy * rstd * gamma[n + 1] + beta[n + 1];
    ov.z = dz * rstd * gamma[n + 2] + beta[n + 2];
    ov.w = dw * rstd * gamma[n + 3] + beta[n + 3];
    *(float4*)(out + (size_t)row * DM_ + n) = ov;
}

// ---------------------------------------------------------------------------
extern "C" void kernel_launch(void* const* d_in, const int* in_sizes, int n_in,
                              void* d_out, int out_size)
{
    const float* Q    = (const float*)d_in[0];
    const float* K    = (const float*)d_in[1];
    const float* V    = (const float*)d_in[2];
    /* d_in[3] = node_num (unused) */
    const int*   mask = (const int*)  d_in[4];
    const float* Wq   = (const float*)d_in[5];
    const float* bq   = (const float*)d_in[6];
    const float* Wk   = (const float*)d_in[7];
    const float* bk   = (const float*)d_in[8];
    const float* Wv   = (const float*)d_in[9];
    const float* bv   = (const float*)d_in[10];
    const float* Wo   = (const float*)d_in[11];
    const float* bo   = (const float*)d_in[12];
    const float* gamma= (const float*)d_in[13];
    const float* beta = (const float*)d_in[14];
    float* out = (float*)d_out;

    cudaFuncSetAttribute(gemm_qkv,   cudaFuncAttributeMaxDynamicSharedMemorySize, GEMM_SMEM);
    cudaFuncSetAttribute(gemm_o,     cudaFuncAttributeMaxDynamicSharedMemorySize, GEMM_SMEM);
    cudaFuncSetAttribute(flash_attn, cudaFuncAttributeMaxDynamicSharedMemorySize, FA_SMEM);

    __half *wt, *x;
    cudaGetSymbolAddress((void**)&wt, g_wt);
    cudaGetSymbolAddress((void**)&x,  g_x);

    // ---- pre-pass conversions ----
    convert_wt_all<<<dim3(16, 16, 4), 256>>>(Wq, Wk, Wv, Wo, wt);
    convert_x_all<<<18432, 256>>>(Q, K, V, x);

    // ---- Q/K/V projections (single merged launch) ----
    gemm_qkv<<<dim3(8, 144), 128, GEMM_SMEM>>>(x, wt, bq, bk, bv);

    // ---- attention (128-q tiles) ----
    flash_attn<<<dim3(LQ_ / 128, H_, B_), 128, FA_SMEM>>>(mask);

    // ---- output projection (split-K x2, raw partials) ----
    gemm_o<<<dim3(8, 16, 2), 128, GEMM_SMEM>>>(wt);

    // ---- layernorm (sums partials + bias + residual) ----
    layernorm_kernel<<<B_ * LQ_, 256>>>(gamma, beta, bo, Q, out);
}